// round 8
// baseline (speedup 1.0000x reference)
#include <cuda_runtime.h>
#include <cuda_bf16.h>
#include <math.h>
#include <stdint.h>

// Problem dims
#define Bb 8
#define Ss 512
#define Ee 512
#define NH 8
#define HDm 64
#define ROWS (Bb*Ss)        // 4096 token rows
#define CLS_H 16000
#define VOC 8000
#define VOC_PAD 8064
#define SQRT_E 22.627416997969522f
#define QK_SCALE 0.04419417382415922f   // 1/sqrt(512)
#define LN_EPS 1e-3f
#define QMAX 16256.0f   // 15-bit quant range: a1 in [-127,127], a2 in [-64,63]

// ---------------- scratch (device globals; no allocations allowed) -------------
__device__ float g_x[ROWS*Ee];
__device__ float g_y[ROWS*Ee];
__device__ float g_q[ROWS*Ee];
__device__ float g_k[ROWS*Ee];
__device__ float g_v[ROWS*Ee];
__device__ float g_att[ROWS*Ee];
__device__ float g_t0[ROWS*Ee];
__device__ float g_t1[ROWS*Ee];
__device__ float g_t2[ROWS*Ee];
__device__ float g_w[Ee*Ee];
__device__ float g_logits[Bb*NH*Ss*Ss];

// bf16 split buffers for classifier GEMM1
__device__ __nv_bfloat16 g_A1h[ROWS*Ee];
__device__ __nv_bfloat16 g_A1l[ROWS*Ee];
__device__ __nv_bfloat16 g_B1h[(size_t)CLS_H*Ee];      // w1^T [16000,512]
__device__ __nv_bfloat16 g_B1l[(size_t)CLS_H*Ee];

// fp32 hidden + int8 quantized buffers for classifier GEMM2
__device__ float  g_hid[(size_t)ROWS*CLS_H];
__device__ int8_t g_A2q1[(size_t)ROWS*CLS_H];
__device__ int8_t g_A2q2[(size_t)ROWS*CLS_H];
__device__ int8_t g_B2q1[(size_t)VOC_PAD*CLS_H];
__device__ int8_t g_B2q2[(size_t)VOC_PAD*CLS_H];
__device__ int   g_rowmax[ROWS];
__device__ int   g_colmax[VOC_PAD];
__device__ float g_sA[ROWS];
__device__ float g_sAinv[ROWS];
__device__ float g_sB[VOC_PAD];
__device__ float g_sBinv[VOC_PAD];

// ================= helpers =================
__device__ __forceinline__ uint32_t smem_u32(const void* p) {
    uint32_t a;
    asm("{ .reg .u64 t; cvta.to.shared.u64 t, %1; cvt.u32.u64 %0, t; }" : "=r"(a) : "l"(p));
    return a;
}
__device__ __forceinline__ void cp16(uint32_t dst, const void* src) {
    asm volatile("cp.async.cg.shared.global [%0], [%1], 16;" :: "r"(dst), "l"(src));
}
__device__ __forceinline__ void cp_commit() { asm volatile("cp.async.commit_group;"); }
__device__ __forceinline__ void cp_wait1()  { asm volatile("cp.async.wait_group 1;"); }

__device__ __forceinline__ void ldsm4(uint32_t* r, uint32_t addr) {
    asm volatile("ldmatrix.sync.aligned.m8n8.x4.shared.b16 {%0,%1,%2,%3}, [%4];"
        : "=r"(r[0]), "=r"(r[1]), "=r"(r[2]), "=r"(r[3]) : "r"(addr));
}
__device__ __forceinline__ void mma_bf16(float* c, const uint32_t* a, const uint32_t* b) {
    asm volatile("mma.sync.aligned.m16n8k16.row.col.f32.bf16.bf16.f32 "
        "{%0,%1,%2,%3}, {%4,%5,%6,%7}, {%8,%9}, {%0,%1,%2,%3};"
        : "+f"(c[0]), "+f"(c[1]), "+f"(c[2]), "+f"(c[3])
        : "r"(a[0]), "r"(a[1]), "r"(a[2]), "r"(a[3]), "r"(b[0]), "r"(b[1]));
}
__device__ __forceinline__ void mma_s8(int* c, const uint32_t* a, const uint32_t* b) {
    asm volatile("mma.sync.aligned.m16n8k32.row.col.s32.s8.s8.s32 "
        "{%0,%1,%2,%3}, {%4,%5,%6,%7}, {%8,%9}, {%0,%1,%2,%3};"
        : "+r"(c[0]), "+r"(c[1]), "+r"(c[2]), "+r"(c[3])
        : "r"(a[0]), "r"(a[1]), "r"(a[2]), "r"(a[3]), "r"(b[0]), "r"(b[1]));
}

// ================= bf16 split GEMM1: hid = relu(A@w1^T + b1), fp32 out + rowmax =====
#define MAT_BYTES 10240            // 128*40*2
#define STAGE_BYTES (4*MAT_BYTES)  // 40960
#define NSTAGE 3

__device__ __forceinline__ void load_stage(
    uint32_t sb, const __nv_bfloat16* Ah, const __nv_bfloat16* Al,
    const __nv_bfloat16* Bh, const __nv_bfloat16* Bl,
    size_t m0, size_t n0, int k0, int lda, int ldb, int t)
{
    const __nv_bfloat16* srcs[4] = { Ah, Al, Bh, Bl };
    #pragma unroll
    for (int p = 0; p < 8; p++) {
        int idx = t + p * 256;           // 0..2047
        int mat = idx >> 9;              // 0..3
        int r   = (idx & 511) >> 2;      // 0..127
        int ch  = idx & 3;               // 16B chunk in row
        size_t grow = (mat < 2 ? m0 : n0) + r;
        int ld = (mat < 2 ? lda : ldb);
        const __nv_bfloat16* src = srcs[mat] + grow * (size_t)ld + k0 + ch * 8;
        cp16(sb + mat * MAT_BYTES + r * 80 + ch * 16, src);
    }
}

__global__ void __launch_bounds__(256) gemm_bf16_relu_kernel(
    const __nv_bfloat16* __restrict__ Ah, const __nv_bfloat16* __restrict__ Al,
    const __nv_bfloat16* __restrict__ Bh, const __nv_bfloat16* __restrict__ Bl,
    const float* __restrict__ bias, float* __restrict__ outf,
    int* __restrict__ rowmax,
    int K, int lda, int ldb, int tiles_n, int ldo)
{
    extern __shared__ char smem[];
    __shared__ int smax[128];
    uint32_t sbase = smem_u32(smem);
    const int t = threadIdx.x;
    const int wid = t >> 5, lane = t & 31;
    const int warp_m = wid & 1, warp_n = wid >> 1;   // 2x4 warps, warp tile 64x32

    if (t < 128) smax[t] = 0;

    const int G = 8;
    int idx = blockIdx.x;
    int band = idx / (G * tiles_n);
    int r = idx % (G * tiles_n);
    size_t m0 = (size_t)(band * G + (r % G)) * 128;
    size_t n0 = (size_t)(r / G) * 128;

    float acc[4][4][4];
    #pragma unroll
    for (int i = 0; i < 4; i++)
        #pragma unroll
        for (int j = 0; j < 4; j++)
            #pragma unroll
            for (int e = 0; e < 4; e++) acc[i][j][e] = 0.0f;

    const int C = K >> 5;   // K chunks of 32
    load_stage(sbase + 0 * STAGE_BYTES, Ah, Al, Bh, Bl, m0, n0, 0,  lda, ldb, t); cp_commit();
    load_stage(sbase + 1 * STAGE_BYTES, Ah, Al, Bh, Bl, m0, n0, 32, lda, ldb, t); cp_commit();

    const int lrow = lane & 15;
    const int lcolb = (lane >> 4) * 16;

    for (int c = 0; c < C; c++) {
        cp_wait1();
        __syncthreads();
        if (c + 2 < C)
            load_stage(sbase + ((c + 2) % NSTAGE) * STAGE_BYTES,
                       Ah, Al, Bh, Bl, m0, n0, (c + 2) * 32, lda, ldb, t);
        cp_commit();

        uint32_t sb = sbase + (c % NSTAGE) * STAGE_BYTES;
        uint32_t aBaseH = sb +                (warp_m * 64 + lrow) * 80;
        uint32_t aBaseL = sb + MAT_BYTES    + (warp_m * 64 + lrow) * 80;
        uint32_t bBaseH = sb + 2*MAT_BYTES  + (warp_n * 32 + lrow) * 80;
        uint32_t bBaseL = sb + 3*MAT_BYTES  + (warp_n * 32 + lrow) * 80;

        #pragma unroll
        for (int ks = 0; ks < 2; ks++) {
            int kb = ks * 32 + lcolb;
            uint32_t ah[4][4], al[4][4], bh[4][2], bl[4][2];
            #pragma unroll
            for (int fm = 0; fm < 4; fm++) {
                ldsm4(ah[fm], aBaseH + fm * 16 * 80 + kb);
                ldsm4(al[fm], aBaseL + fm * 16 * 80 + kb);
            }
            #pragma unroll
            for (int fp = 0; fp < 2; fp++) {
                uint32_t rr[4];
                ldsm4(rr, bBaseH + fp * 16 * 80 + kb);
                bh[fp*2][0] = rr[0]; bh[fp*2][1] = rr[2];
                bh[fp*2+1][0] = rr[1]; bh[fp*2+1][1] = rr[3];
                ldsm4(rr, bBaseL + fp * 16 * 80 + kb);
                bl[fp*2][0] = rr[0]; bl[fp*2][1] = rr[2];
                bl[fp*2+1][0] = rr[1]; bl[fp*2+1][1] = rr[3];
            }
            #pragma unroll
            for (int fm = 0; fm < 4; fm++)
                #pragma unroll
                for (int fn = 0; fn < 4; fn++) {
                    mma_bf16(acc[fm][fn], ah[fm], bh[fn]);
                    mma_bf16(acc[fm][fn], al[fm], bh[fn]);
                    mma_bf16(acc[fm][fn], ah[fm], bl[fn]);
                }
        }
        __syncthreads();
    }

    // epilogue: relu, fp32 out, per-row max (values >= 0 -> int-compare trick)
    const int g = lane >> 2;
    const int cq = (lane & 3) * 2;
    float rmax[4][2];
    #pragma unroll
    for (int i = 0; i < 4; i++) { rmax[i][0] = 0.f; rmax[i][1] = 0.f; }

    #pragma unroll
    for (int fm = 0; fm < 4; fm++) {
        #pragma unroll
        for (int fn = 0; fn < 4; fn++) {
            int colbase = (int)n0 + warp_n * 32 + fn * 8 + cq;
            float b0 = bias[colbase], b1 = bias[colbase + 1];
            #pragma unroll
            for (int hrow = 0; hrow < 2; hrow++) {
                size_t row = m0 + warp_m * 64 + fm * 16 + g + hrow * 8;
                float v0 = fmaxf(acc[fm][fn][hrow * 2 + 0] + b0, 0.0f);
                float v1 = fmaxf(acc[fm][fn][hrow * 2 + 1] + b1, 0.0f);
                rmax[fm][hrow] = fmaxf(rmax[fm][hrow], fmaxf(v0, v1));
                float2 fv; fv.x = v0; fv.y = v1;
                *reinterpret_cast<float2*>(&outf[row * (size_t)ldo + colbase]) = fv;
            }
        }
    }
    #pragma unroll
    for (int fm = 0; fm < 4; fm++)
        #pragma unroll
        for (int hrow = 0; hrow < 2; hrow++)
            atomicMax(&smax[warp_m * 64 + fm * 16 + g + hrow * 8],
                      __float_as_int(rmax[fm][hrow]));
    __syncthreads();
    if (t < 128) atomicMax(&rowmax[m0 + t], smax[t]);
}

// ================= int8 IMMA GEMM2: out = sA*sB*(A15 . B15) + bias =================
// A = sA*(128*a1 + a2), B = sB*(128*b1 + b2); acc1 = sum a1*b1, accX = sum(a1*b2 + a2*b1)
// C = qa*qb*(16384*acc1 + 128*accX) + bias     (a2*b2 term dropped, ~1e-4 rel)
#define IMAT 6144                 // 128 rows * 48B stride
#define ISTAGE (4*IMAT)           // 24576
#define INSTAGE 3

__device__ __forceinline__ void load_stage_i8(
    uint32_t sb, const int8_t* A1, const int8_t* A2,
    const int8_t* B1, const int8_t* B2,
    size_t m0, size_t n0, int k0, int ld, int t)
{
    const int8_t* srcs[4] = { A1, A2, B1, B2 };
    #pragma unroll
    for (int p = 0; p < 4; p++) {
        int idx = t + p * 256;        // 0..1023
        int mat = idx >> 8;           // 0..3
        int r   = (idx & 255) >> 1;   // 0..127
        int ch  = idx & 1;
        size_t grow = (mat < 2 ? m0 : n0) + r;
        cp16(sb + mat * IMAT + r * 48 + ch * 16,
             srcs[mat] + grow * (size_t)ld + k0 + ch * 16);
    }
}

__global__ void __launch_bounds__(256) gemm_imma_kernel(
    const int8_t* __restrict__ Aq1, const int8_t* __restrict__ Aq2,
    const int8_t* __restrict__ Bq1, const int8_t* __restrict__ Bq2,
    const float* __restrict__ sA, const float* __restrict__ sB,
    const float* __restrict__ bias, float* __restrict__ outf,
    int K, int ld, int tiles_n, int Nreal, int ldo)
{
    extern __shared__ char smem[];
    uint32_t sbase = smem_u32(smem);
    const int t = threadIdx.x;
    const int wid = t >> 5, lane = t & 31;
    const int warp_m = wid & 1, warp_n = wid >> 1;

    const int G = 8;
    int idx = blockIdx.x;
    int band = idx / (G * tiles_n);
    int r = idx % (G * tiles_n);
    size_t m0 = (size_t)(band * G + (r % G)) * 128;
    size_t n0 = (size_t)(r / G) * 128;

    int acc1[4][4][4], accX[4][4][4];
    #pragma unroll
    for (int i = 0; i < 4; i++)
        #pragma unroll
        for (int j = 0; j < 4; j++)
            #pragma unroll
            for (int e = 0; e < 4; e++) { acc1[i][j][e] = 0; accX[i][j][e] = 0; }

    const int C = K >> 5;   // k chunks of 32 bytes
    load_stage_i8(sbase + 0 * ISTAGE, Aq1, Aq2, Bq1, Bq2, m0, n0, 0,  ld, t); cp_commit();
    load_stage_i8(sbase + 1 * ISTAGE, Aq1, Aq2, Bq1, Bq2, m0, n0, 32, ld, t); cp_commit();

    const int lrow = lane & 15;
    const int lcolb = (lane >> 4) * 16;

    for (int c = 0; c < C; c++) {
        cp_wait1();
        __syncthreads();
        if (c + 2 < C)
            load_stage_i8(sbase + ((c + 2) % INSTAGE) * ISTAGE,
                          Aq1, Aq2, Bq1, Bq2, m0, n0, (c + 2) * 32, ld, t);
        cp_commit();

        uint32_t sb = sbase + (c % INSTAGE) * ISTAGE;
        uint32_t aB1 = sb            + (warp_m * 64 + lrow) * 48;
        uint32_t aB2 = sb + IMAT     + (warp_m * 64 + lrow) * 48;
        uint32_t bB1 = sb + 2*IMAT   + (warp_n * 32 + lrow) * 48;
        uint32_t bB2 = sb + 3*IMAT   + (warp_n * 32 + lrow) * 48;

        uint32_t a1f[4][4], a2f[4][4], b1f[4][2], b2f[4][2];
        #pragma unroll
        for (int fm = 0; fm < 4; fm++) {
            ldsm4(a1f[fm], aB1 + fm * 16 * 48 + lcolb);
            ldsm4(a2f[fm], aB2 + fm * 16 * 48 + lcolb);
        }
        #pragma unroll
        for (int fp = 0; fp < 2; fp++) {
            uint32_t rr[4];
            ldsm4(rr, bB1 + fp * 16 * 48 + lcolb);
            b1f[fp*2][0] = rr[0]; b1f[fp*2][1] = rr[2];
            b1f[fp*2+1][0] = rr[1]; b1f[fp*2+1][1] = rr[3];
            ldsm4(rr, bB2 + fp * 16 * 48 + lcolb);
            b2f[fp*2][0] = rr[0]; b2f[fp*2][1] = rr[2];
            b2f[fp*2+1][0] = rr[1]; b2f[fp*2+1][1] = rr[3];
        }
        #pragma unroll
        for (int fm = 0; fm < 4; fm++)
            #pragma unroll
            for (int fn = 0; fn < 4; fn++) {
                mma_s8(acc1[fm][fn], a1f[fm], b1f[fn]);
                mma_s8(accX[fm][fn], a1f[fm], b2f[fn]);
                mma_s8(accX[fm][fn], a2f[fm], b1f[fn]);
            }
        __syncthreads();
    }

    const int g = lane >> 2;
    const int cq = (lane & 3) * 2;
    #pragma unroll
    for (int fm = 0; fm < 4; fm++) {
        #pragma unroll
        for (int fn = 0; fn < 4; fn++) {
            int colbase = (int)n0 + warp_n * 32 + fn * 8 + cq;
            if (colbase < Nreal) {
                float qb0 = sB[colbase], qb1 = sB[colbase + 1];
                float bi0 = bias[colbase], bi1 = bias[colbase + 1];
                #pragma unroll
                for (int hrow = 0; hrow < 2; hrow++) {
                    size_t row = m0 + warp_m * 64 + fm * 16 + g + hrow * 8;
                    float qa = sA[row];
                    float g0 = fmaf((float)acc1[fm][fn][hrow*2+0], 128.0f,
                                    (float)accX[fm][fn][hrow*2+0]);
                    float g1 = fmaf((float)acc1[fm][fn][hrow*2+1], 128.0f,
                                    (float)accX[fm][fn][hrow*2+1]);
                    float v0 = fmaf(g0, 128.0f * qa * qb0, bi0);
                    float v1 = fmaf(g1, 128.0f * qa * qb1, bi1);
                    float2 fv; fv.x = v0; fv.y = v1;
                    *reinterpret_cast<float2*>(&outf[row * (size_t)ldo + colbase]) = fv;
                }
            }
        }
    }
}

// ---------------- quantization prep ----------------
__global__ __launch_bounds__(256) void zero_kernel(int* __restrict__ p, int n)
{
    int i = blockIdx.x * 256 + threadIdx.x;
    if (i < n) p[i] = 0;
}

// column abs-max of w [K,N] -> cmax[n] (float bits in int, via atomicMax)
__global__ __launch_bounds__(256) void colmax_kernel(
    const float* __restrict__ w, int* __restrict__ cmax, int K, int N)
{
    __shared__ float red[8][33];
    int n0 = blockIdx.x * 32, k0 = blockIdx.y * 32;
    int tx = threadIdx.x & 31, ty = threadIdx.x >> 5;
    float m = 0.0f;
    int nn = n0 + tx;
    #pragma unroll
    for (int j = 0; j < 4; j++) {
        int kk = k0 + ty + j * 8;
        if (nn < N) m = fmaxf(m, fabsf(w[(size_t)kk * N + nn]));
    }
    red[ty][tx] = m;
    __syncthreads();
    if (ty == 0) {
        #pragma unroll
        for (int i = 1; i < 8; i++) m = fmaxf(m, red[i][tx]);
        if (nn < N) atomicMax(&cmax[nn], __float_as_int(m));
    }
}

__global__ __launch_bounds__(256) void finalize_kernel(
    const int* __restrict__ maxbuf, float* __restrict__ s, float* __restrict__ sinv, int n)
{
    int i = blockIdx.x * 256 + threadIdx.x;
    if (i < n) {
        float m = __int_as_float(maxbuf[i]);
        s[i] = m * (1.0f / QMAX);
        sinv[i] = (m > 0.0f) ? (QMAX / m) : 0.0f;
    }
}

// transpose + quantize: w [K,N] fp32 -> q1/q2 [Npad,K] int8 with per-col scales
__global__ __launch_bounds__(256) void quantB_kernel(
    const float* __restrict__ w, const float* __restrict__ sinv,
    int8_t* __restrict__ q1, int8_t* __restrict__ q2, int K, int N)
{
    __shared__ float tile[32][33];
    int n0 = blockIdx.x * 32, k0 = blockIdx.y * 32;
    int tx = threadIdx.x & 31, ty = threadIdx.x >> 5;
    #pragma unroll
    for (int j = 0; j < 4; j++) {
        int kk = k0 + ty + j * 8;
        int nn = n0 + tx;
        tile[ty + j * 8][tx] = (nn < N) ? w[(size_t)kk * N + nn] : 0.0f;
    }
    __syncthreads();
    #pragma unroll
    for (int j = 0; j < 4; j++) {
        int nn = n0 + ty + j * 8;
        int kk = k0 + tx;
        float si = sinv[nn];
        int ai = __float2int_rn(tile[tx][ty + j * 8] * si);
        int a1 = (ai + 64) >> 7;
        int a2 = ai - (a1 << 7);
        q1[(size_t)nn * K + kk] = (int8_t)a1;
        q2[(size_t)nn * K + kk] = (int8_t)a2;
    }
}

// quantize hidden [ROWS, N] with per-row scales
__global__ __launch_bounds__(256) void quantA_kernel(
    const float* __restrict__ hid, const float* __restrict__ sinv,
    int8_t* __restrict__ q1, int8_t* __restrict__ q2, int N)
{
    int row = blockIdx.y;
    int col = blockIdx.x * 256 + threadIdx.x;
    if (col < N) {
        float si = sinv[row];
        int ai = __float2int_rn(hid[(size_t)row * N + col] * si);
        int a1 = (ai + 64) >> 7;
        int a2 = ai - (a1 << 7);
        q1[(size_t)row * N + col] = (int8_t)a1;
        q2[(size_t)row * N + col] = (int8_t)a2;
    }
}

// ---------------- fp32 -> bf16 hi/lo split (elementwise) ----------------
__global__ __launch_bounds__(256) void split_kernel(
    const float* __restrict__ in, __nv_bfloat16* __restrict__ oh,
    __nv_bfloat16* __restrict__ ol, int count)
{
    int i = blockIdx.x * 256 + threadIdx.x;
    if (i < count) {
        float v = in[i];
        __nv_bfloat16 h = __float2bfloat16(v);
        oh[i] = h;
        ol[i] = __float2bfloat16(v - __bfloat162float(h));
    }
}

// ---------------- transpose + split: fp32 [K,N] -> bf16 [N,K] hi/lo ----------------
__global__ __launch_bounds__(256) void transpose_split_kernel(
    const float* __restrict__ in, __nv_bfloat16* __restrict__ oh,
    __nv_bfloat16* __restrict__ ol, int K, int N)
{
    __shared__ float tile[32][33];
    int n0 = blockIdx.x * 32, k0 = blockIdx.y * 32;
    int tx = threadIdx.x & 31, ty = threadIdx.x >> 5;
    #pragma unroll
    for (int j = 0; j < 4; j++) {
        int kk = k0 + ty + j * 8;
        int nn = n0 + tx;
        tile[ty + j * 8][tx] = (nn < N) ? in[(size_t)kk * N + nn] : 0.0f;
    }
    __syncthreads();
    #pragma unroll
    for (int j = 0; j < 4; j++) {
        int nn = n0 + ty + j * 8;
        int kk = k0 + tx;
        float v = tile[tx][ty + j * 8];
        __nv_bfloat16 h = __float2bfloat16(v);
        oh[(size_t)nn * K + kk] = h;
        ol[(size_t)nn * K + kk] = __float2bfloat16(v - __bfloat162float(h));
    }
}

// ---------------- embedding + positional encoding ----------------
__global__ __launch_bounds__(256) void embed_kernel(
    const int* __restrict__ ids, const float* __restrict__ emb, float* __restrict__ out)
{
    int bs = blockIdx.x;
    int s  = bs & (Ss - 1);
    int id = ids[bs];
    const float* erow = emb + (size_t)id * Ee;
    float* orow = out + (size_t)bs * Ee;
    for (int e = threadIdx.x; e < Ee; e += blockDim.x) {
        int i = e & 255;
        float rate = expf(-(float)i * (9.210340371976184f / 256.0f));
        float ang = (float)s * rate;
        float p = (e < 256) ? sinf(ang) : cosf(ang);
        orow[e] = erow[e] * SQRT_E + p;
    }
}

// ---------------- repack [H,E,HD] -> [E, H*HD] ----------------
__global__ __launch_bounds__(256) void repack_kernel(
    const float* __restrict__ w, float* __restrict__ out)
{
    int e = blockIdx.x;
    for (int j = threadIdx.x; j < Ee; j += blockDim.x)
        out[e * Ee + j] = w[(j >> 6) * (Ee * HDm) + e * HDm + (j & 63)];
}

// ---------------- fp32 tiled SGEMM (E-size ops) ----------------
__global__ __launch_bounds__(256) void sgemm_kernel(
    const float* __restrict__ A, const float* __restrict__ B,
    const float* __restrict__ bias, float* __restrict__ C,
    int M, int N, int K, int relu)
{
    __shared__ float As[16][128];
    __shared__ float Bs[16][128];
    const int t  = threadIdx.x;
    const int tx = t & 15, ty = t >> 4;
    const int row0 = blockIdx.y * 128, col0 = blockIdx.x * 128;
    const int aRow = t >> 2, aCol = (t & 3) * 4;
    const int bRow = t >> 5, bCol = (t & 31) * 4;

    float acc[8][8];
    #pragma unroll
    for (int i = 0; i < 8; i++)
        #pragma unroll
        for (int j = 0; j < 8; j++) acc[i][j] = 0.0f;

    for (int k0 = 0; k0 < K; k0 += 16) {
        #pragma unroll
        for (int p = 0; p < 2; p++) {
            int m = aRow + p * 64;
            float4 vA = *reinterpret_cast<const float4*>(&A[(size_t)(row0 + m) * K + k0 + aCol]);
            As[aCol + 0][m] = vA.x; As[aCol + 1][m] = vA.y;
            As[aCol + 2][m] = vA.z; As[aCol + 3][m] = vA.w;
        }
        #pragma unroll
        for (int p = 0; p < 2; p++) {
            int kk = bRow + p * 8;
            int c = col0 + bCol;
            float4 vB = make_float4(0.f, 0.f, 0.f, 0.f);
            if (c < N) vB = *reinterpret_cast<const float4*>(&B[(size_t)(k0 + kk) * N + c]);
            *reinterpret_cast<float4*>(&Bs[kk][bCol]) = vB;
        }
        __syncthreads();
        #pragma unroll
        for (int kk = 0; kk < 16; kk++) {
            float ra[8], rb[8];
            float4 a0 = *reinterpret_cast<const float4*>(&As[kk][ty * 8]);
            float4 a1 = *reinterpret_cast<const float4*>(&As[kk][ty * 8 + 4]);
            float4 b0 = *reinterpret_cast<const float4*>(&Bs[kk][tx * 8]);
            float4 b1 = *reinterpret_cast<const float4*>(&Bs[kk][tx * 8 + 4]);
            ra[0]=a0.x; ra[1]=a0.y; ra[2]=a0.z; ra[3]=a0.w;
            ra[4]=a1.x; ra[5]=a1.y; ra[6]=a1.z; ra[7]=a1.w;
            rb[0]=b0.x; rb[1]=b0.y; rb[2]=b0.z; rb[3]=b0.w;
            rb[4]=b1.x; rb[5]=b1.y; rb[6]=b1.z; rb[7]=b1.w;
            #pragma unroll
            for (int i = 0; i < 8; i++)
                #pragma unroll
                for (int j = 0; j < 8; j++)
                    acc[i][j] += ra[i] * rb[j];
        }
        __syncthreads();
    }
    #pragma unroll
    for (int i = 0; i < 8; i++) {
        int m = row0 + ty * 8 + i;
        #pragma unroll
        for (int j = 0; j < 8; j++) {
            int c = col0 + tx * 8 + j;
            if (c < N) {
                float val = acc[i][j];
                if (bias) val += bias[c];
                if (relu) val = fmaxf(val, 0.0f);
                C[(size_t)m * N + c] = val;
            }
        }
    }
}

// ---------------- QK^T + scale + causal ----------------
__global__ __launch_bounds__(256) void qk_kernel(
    const float* __restrict__ Q, const float* __restrict__ Km,
    float* __restrict__ L, int causal)
{
    __shared__ float Qs[64][68];
    __shared__ float Ks[64][68];
    int bh = blockIdx.z, b = bh >> 3, h = bh & 7;
    int q0 = blockIdx.y * 64, k0 = blockIdx.x * 64;
    int t = threadIdx.x;
    #pragma unroll
    for (int p = 0; p < 4; p++) {
        int idx = t + p * 256;
        int r = idx >> 4, f4 = (idx & 15) * 4;
        *reinterpret_cast<float4*>(&Qs[r][f4]) =
            *reinterpret_cast<const float4*>(&Q[(size_t)(b * Ss + q0 + r) * Ee + h * HDm + f4]);
        *reinterpret_cast<float4*>(&Ks[r][f4]) =
            *reinterpret_cast<const float4*>(&Km[(size_t)(b * Ss + k0 + r) * Ee + h * HDm + f4]);
    }
    __syncthreads();
    int tx = t & 15, ty = t >> 4;
    float acc[4][4] = {};
    #pragma unroll 4
    for (int d = 0; d < 64; d++) {
        float ra[4], rb[4];
        #pragma unroll
        for (int i = 0; i < 4; i++) ra[i] = Qs[ty * 4 + i][d];
        #pragma unroll
        for (int j = 0; j < 4; j++) rb[j] = Ks[tx * 4 + j][d];
        #pragma unroll
        for (int i = 0; i < 4; i++)
            #pragma unroll
            for (int j = 0; j < 4; j++)
                acc[i][j] += ra[i] * rb[j];
    }
    #pragma unroll
    for (int i = 0; i < 4; i++) {
        int qi = q0 + ty * 4 + i;
        #pragma unroll
        for (int j = 0; j < 4; j++) {
            int ki = k0 + tx * 4 + j;
            float v = acc[i][j] * QK_SCALE;
            if (causal && ki > qi) v = -INFINITY;
            L[((size_t)bh * Ss + qi) * Ss + ki] = v;
        }
    }
}

// ---------------- row softmax ----------------
__global__ __launch_bounds__(256) void softmax_kernel(float* __restrict__ L)
{
    __shared__ float red[256];
    float* row = L + (size_t)blockIdx.x * Ss;
    int t = threadIdx.x;
    float a = row[t], b = row[t + 256];
    red[t] = fmaxf(a, b);
    __syncthreads();
    for (int s = 128; s > 0; s >>= 1) { if (t < s) red[t] = fmaxf(red[t], red[t + s]); __syncthreads(); }
    float m = red[0];
    __syncthreads();
    float e0 = expf(a - m), e1 = expf(b - m);
    red[t] = e0 + e1;
    __syncthreads();
    for (int s = 128; s > 0; s >>= 1) { if (t < s) red[t] += red[t + s]; __syncthreads(); }
    float inv = 1.0f / red[0];
    row[t] = e0 * inv;
    row[t + 256] = e1 * inv;
}

// ---------------- P @ V ----------------
__global__ __launch_bounds__(256) void pv_kernel(
    const float* __restrict__ P, const float* __restrict__ V, float* __restrict__ O)
{
    __shared__ float Ps[64][68];
    __shared__ float Vs[64][68];
    int bh = blockIdx.y, b = bh >> 3, h = bh & 7;
    int q0 = blockIdx.x * 64;
    int t = threadIdx.x, tx = t & 15, ty = t >> 4;
    float acc[4][4] = {};
    for (int k0 = 0; k0 < Ss; k0 += 64) {
        #pragma unroll
        for (int p = 0; p < 4; p++) {
            int idx = t + p * 256;
            int r = idx >> 4, f4 = (idx & 15) * 4;
            *reinterpret_cast<float4*>(&Ps[r][f4]) =
                *reinterpret_cast<const float4*>(&P[((size_t)bh * Ss + q0 + r) * Ss + k0 + f4]);
            *reinterpret_cast<float4*>(&Vs[r][f4]) =
                *reinterpret_cast<const float4*>(&V[(size_t)(b * Ss + k0 + r) * Ee + h * HDm + f4]);
        }
        __syncthreads();
        #pragma unroll 4
        for (int kk = 0; kk < 64; kk++) {
            float ra[4], rb[4];
            #pragma unroll
            for (int i = 0; i < 4; i++) ra[i] = Ps[ty * 4 + i][kk];
            #pragma unroll
            for (int j = 0; j < 4; j++) rb[j] = Vs[kk][tx * 4 + j];
            #pragma unroll
            for (int i = 0; i < 4; i++)
                #pragma unroll
                for (int j = 0; j < 4; j++)
                    acc[i][j] += ra[i] * rb[j];
        }
        __syncthreads();
    }
    #pragma unroll
    for (int i = 0; i < 4; i++)
        #pragma unroll
        for (int j = 0; j < 4; j++)
            O[(size_t)(b * Ss + q0 + ty * 4 + i) * Ee + h * HDm + tx * 4 + j] = acc[i][j];
}

// ---------------- LN(A + R)*g + b (opt relu) ----------------
__global__ __launch_bounds__(256) void ln_kernel(
    const float* __restrict__ A, const float* __restrict__ R,
    const float* __restrict__ g, const float* __restrict__ be,
    float* __restrict__ out, int relu)
{
    __shared__ float red[256];
    size_t row = blockIdx.x;
    int t = threadIdx.x;
    float a0 = A[row * Ee + t] + R[row * Ee + t];
    float a1 = A[row * Ee + t + 256] + R[row * Ee + t + 256];
    red[t] = a0 + a1;
    __syncthreads();
    for (int s = 128; s > 0; s >>= 1) { if (t < s) red[t] += red[t + s]; __syncthreads(); }
    float mean = red[0] * (1.0f / Ee);
    __syncthreads();
    float d0 = a0 - mean, d1 = a1 - mean;
    red[t] = d0 * d0 + d1 * d1;
    __syncthreads();
    for (int s = 128; s > 0; s >>= 1) { if (t < s) red[t] += red[t + s]; __syncthreads(); }
    float var = red[0] * (1.0f / Ee);
    float inv = rsqrtf(var + LN_EPS);
    float v0 = d0 * inv * g[t] + be[t];
    float v1 = d1 * inv * g[t + 256] + be[t + 256];
    if (relu) { v0 = fmaxf(v0, 0.0f); v1 = fmaxf(v1, 0.0f); }
    out[row * Ee + t] = v0;
    out[row * Ee + t + 256] = v1;
}

// ---------------- host orchestration ----------------
static inline void launch_gemm(const float* A, const float* B, const float* bias,
                               float* C, int M, int N, int K, int relu)
{
    dim3 grid((N + 127) / 128, M / 128);
    sgemm_kernel<<<grid, 256>>>(A, B, bias, C, M, N, K, relu);
}

extern "C" void kernel_launch(void* const* d_in, const int* in_sizes, int n_in,
                              void* d_out, int out_size)
{
    const int*   src_ids  = (const int*)  d_in[0];
    const int*   tgt_ids  = (const int*)  d_in[1];
    const float* src_emb  = (const float*)d_in[2];
    const float* tgt_emb  = (const float*)d_in[3];
    const float* enc_wk   = (const float*)d_in[4];
    const float* enc_wv   = (const float*)d_in[5];
    const float* enc_wq   = (const float*)d_in[6];
    const float* enc_dw   = (const float*)d_in[7];
    const float* enc_db   = (const float*)d_in[8];
    const float* enc_ffw  = (const float*)d_in[9];
    const float* enc_ffb  = (const float*)d_in[10];
    const float* enc_ln_g = (const float*)d_in[11];
    const float* enc_ln_b = (const float*)d_in[12];
    const float* dec_swk  = (const float*)d_in[13];
    const float* dec_swv  = (const float*)d_in[14];
    const float* dec_swq  = (const float*)d_in[15];
    const float* dec_sdw  = (const float*)d_in[16];
    const float* dec_sdb  = (const float*)d_in[17];
    const float* dec_cwk  = (const float*)d_in[18];
    const float* dec_cwv  = (const float*)d_in[19];
    const float* dec_cwq  = (const float*)d_in[20];
    const float* dec_cdw  = (const float*)d_in[21];
    const float* dec_cdb  = (const float*)d_in[22];
    const float* dec_ffw  = (const float*)d_in[23];
    const float* dec_ffb  = (const float*)d_in[24];
    const float* dec_ln_g = (const float*)d_in[25];
    const float* dec_ln_b = (const float*)d_in[26];
    const float* cls_w1   = (const float*)d_in[27];
    const float* cls_b1   = (const float*)d_in[28];
    const float* cls_w2   = (const float*)d_in[29];
    const float* cls_b2   = (const float*)d_in[30];

    float *x, *y, *q, *k, *v, *att, *t0, *t1, *t2, *w, *logits, *hid;
    __nv_bfloat16 *A1h, *A1l, *B1h, *B1l;
    int8_t *A2q1, *A2q2, *B2q1, *B2q2;
    int *rowmax, *colmax;
    float *sA, *sAinv, *sB, *sBinv;
    cudaGetSymbolAddress((void**)&x,      g_x);
    cudaGetSymbolAddress((void**)&y,      g_y);
    cudaGetSymbolAddress((void**)&q,      g_q);
    cudaGetSymbolAddress((void**)&k,      g_k);
    cudaGetSymbolAddress((void**)&v,      g_v);
    cudaGetSymbolAddress((void**)&att,    g_att);
    cudaGetSymbolAddress((void**)&t0,     g_t0);
    cudaGetSymbolAddress((void**)&t1,     g_t1);
    cudaGetSymbolAddress((void**)&t2,     g_t2);
    cudaGetSymbolAddress((void**)&w,      g_w);
    cudaGetSymbolAddress((void**)&logits, g_logits);
    cudaGetSymbolAddress((void**)&hid,    g_hid);
    cudaGetSymbolAddress((void**)&A1h, g_A1h);
    cudaGetSymbolAddress((void**)&A1l, g_A1l);
    cudaGetSymbolAddress((void**)&B1h, g_B1h);
    cudaGetSymbolAddress((void**)&B1l, g_B1l);
    cudaGetSymbolAddress((void**)&A2q1, g_A2q1);
    cudaGetSymbolAddress((void**)&A2q2, g_A2q2);
    cudaGetSymbolAddress((void**)&B2q1, g_B2q1);
    cudaGetSymbolAddress((void**)&B2q2, g_B2q2);
    cudaGetSymbolAddress((void**)&rowmax, g_rowmax);
    cudaGetSymbolAddress((void**)&colmax, g_colmax);
    cudaGetSymbolAddress((void**)&sA,    g_sA);
    cudaGetSymbolAddress((void**)&sAinv, g_sAinv);
    cudaGetSymbolAddress((void**)&sB,    g_sB);
    cudaGetSymbolAddress((void**)&sBinv, g_sBinv);

    cudaFuncSetAttribute(gemm_bf16_relu_kernel, cudaFuncAttributeMaxDynamicSharedMemorySize,
                         NSTAGE * STAGE_BYTES);
    cudaFuncSetAttribute(gemm_imma_kernel, cudaFuncAttributeMaxDynamicSharedMemorySize,
                         INSTAGE * ISTAGE);

    // ---- classifier prep (weights only; independent of activations) ----
    zero_kernel<<<(ROWS + 255) / 256, 256>>>(rowmax, ROWS);
    zero_kernel<<<(VOC_PAD + 255) / 256, 256>>>(colmax, VOC_PAD);
    colmax_kernel<<<dim3(VOC_PAD / 32, CLS_H / 32), 256>>>(cls_w2, colmax, CLS_H, VOC);
    finalize_kernel<<<(VOC_PAD + 255) / 256, 256>>>(colmax, sB, sBinv, VOC_PAD);
    quantB_kernel<<<dim3(VOC_PAD / 32, CLS_H / 32), 256>>>(cls_w2, sBinv, B2q1, B2q2, CLS_H, VOC);
    transpose_split_kernel<<<dim3(CLS_H / 32, Ee / 32), 256>>>(cls_w1, B1h, B1l, Ee, CLS_H);

    // embeddings + positional encoding
    embed_kernel<<<ROWS, 256>>>(src_ids, src_emb, x);
    embed_kernel<<<ROWS, 256>>>(tgt_ids, tgt_emb, y);

    #define RUN_MHA(Xk, Xv, Xq, wk_, wv_, wq_, dw_, db_, OUT, CAUSAL)              \
        do {                                                                       \
            repack_kernel<<<Ee, 256>>>((wq_), w);                                  \
            launch_gemm((Xq), w, nullptr, q, ROWS, Ee, Ee, 0);                     \
            repack_kernel<<<Ee, 256>>>((wk_), w);                                  \
            launch_gemm((Xk), w, nullptr, k, ROWS, Ee, Ee, 0);                     \
            repack_kernel<<<Ee, 256>>>((wv_), w);                                  \
            launch_gemm((Xv), w, nullptr, v, ROWS, Ee, Ee, 0);                     \
            qk_kernel<<<dim3(8, 8, Bb * NH), 256>>>(q, k, logits, (CAUSAL));       \
            softmax_kernel<<<Bb * NH * Ss, 256>>>(logits);                         \
            pv_kernel<<<dim3(8, Bb * NH), 256>>>(logits, v, att);                  \
            launch_gemm(att, (dw_), (db_), (OUT), ROWS, Ee, Ee, 0);                \
        } while (0)

    // ---- encoder ----
    RUN_MHA(x, x, x, enc_wk, enc_wv, enc_wq, enc_dw, enc_db, t0, 1);
    ln_kernel<<<ROWS, 256>>>(x, t0, enc_ln_g, enc_ln_b, t1, 0);
    launch_gemm(t1, enc_ffw, enc_ffb, t2, ROWS, Ee, Ee, 0);
    ln_kernel<<<ROWS, 256>>>(t1, t2, enc_ln_g, enc_ln_b, x, 0);

    // ---- decoder ----
    RUN_MHA(y, y, y, dec_swk, dec_swv, dec_swq, dec_sdw, dec_sdb, t0, 1);
    ln_kernel<<<ROWS, 256>>>(t0, y, dec_ln_g, dec_ln_b, t1, 0);
    RUN_MHA(x, x, t1, dec_cwk, dec_cwv, dec_cwq, dec_cdw, dec_cdb, t0, 0);
    ln_kernel<<<ROWS, 256>>>(t0, t1, dec_ln_g, dec_ln_b, t2, 0);
    launch_gemm(t2, dec_ffw, dec_ffb, t0, ROWS, Ee, Ee, 0);
    ln_kernel<<<ROWS, 256>>>(t0, t2, dec_ln_g, dec_ln_b, t1, 1);  // dec_out

    // ---- classifier GEMM1 (bf16 split HMMA): hid = relu(dec_out@w1 + b1), fp32 + rowmax
    split_kernel<<<(ROWS * Ee + 255) / 256, 256>>>(t1, A1h, A1l, ROWS * Ee);
    gemm_bf16_relu_kernel<<<(ROWS / 128) * (CLS_H / 128), 256, NSTAGE * STAGE_BYTES>>>(
        A1h, A1l, B1h, B1l, cls_b1, hid, rowmax,
        Ee, Ee, Ee, CLS_H / 128, CLS_H);

    // ---- quantize hidden, then int8 IMMA GEMM2 ----
    finalize_kernel<<<(ROWS + 255) / 256, 256>>>(rowmax, sA, sAinv, ROWS);
    quantA_kernel<<<dim3((CLS_H + 255) / 256, ROWS), 256>>>(hid, sAinv, A2q1, A2q2, CLS_H);

    gemm_imma_kernel<<<(ROWS / 128) * (VOC_PAD / 128), 256, INSTAGE * ISTAGE>>>(
        A2q1, A2q2, B2q1, B2q2, sA, sB, cls_b2, (float*)d_out,
        CLS_H, CLS_H, VOC_PAD / 128, VOC, VOC);

    #undef RUN_MHA
}

// round 12
// speedup vs baseline: 4.4414x; 4.4414x over previous
#include <cuda_runtime.h>
#include <cuda_bf16.h>
#include <cuda_fp16.h>
#include <math.h>
#include <stdint.h>

// Problem dims
#define Bb 8
#define Ss 512
#define Ee 512
#define NH 8
#define HDm 64
#define ROWS (Bb*Ss)        // 4096 token rows
#define CLS_H 16000
#define VOC 8000
#define VOC_PAD 8064
#define SQRT_E 22.627416997969522f
#define QK_SCALE 0.04419417382415922f   // 1/sqrt(512)
#define LN_EPS 1e-3f

// ---------------- scratch (device globals; no allocations allowed) -------------
__device__ float g_x[ROWS*Ee];
__device__ float g_y[ROWS*Ee];
__device__ float g_q[ROWS*Ee];
__device__ float g_k[ROWS*Ee];
__device__ float g_v[ROWS*Ee];
__device__ float g_att[ROWS*Ee];
__device__ float g_t0[ROWS*Ee];
__device__ float g_t1[ROWS*Ee];
__device__ float g_t2[ROWS*Ee];
__device__ float g_w[Ee*Ee];
__device__ float g_logits[Bb*NH*Ss*Ss];

// classifier GEMM1 (bf16 3-term split, proven accurate)
__device__ __nv_bfloat16 g_A1h[ROWS*Ee];
__device__ __nv_bfloat16 g_A1l[ROWS*Ee];
__device__ __nv_bfloat16 g_B1h[(size_t)CLS_H*Ee];      // w1^T [16000,512]
__device__ __nv_bfloat16 g_B1l[(size_t)CLS_H*Ee];

// classifier GEMM2 (single fp16)
__device__ __half g_A2[(size_t)ROWS*CLS_H];            // hidden fp16 [4096,16000]
__device__ __half g_B2[(size_t)VOC_PAD*CLS_H];         // w2^T fp16 padded [8064,16000]

// ================= helpers =================
__device__ __forceinline__ uint32_t smem_u32(const void* p) {
    uint32_t a;
    asm("{ .reg .u64 t; cvta.to.shared.u64 t, %1; cvt.u32.u64 %0, t; }" : "=r"(a) : "l"(p));
    return a;
}
__device__ __forceinline__ void cp16(uint32_t dst, const void* src) {
    asm volatile("cp.async.cg.shared.global [%0], [%1], 16;" :: "r"(dst), "l"(src));
}
__device__ __forceinline__ void cp_commit() { asm volatile("cp.async.commit_group;"); }
__device__ __forceinline__ void cp_wait1()  { asm volatile("cp.async.wait_group 1;"); }

__device__ __forceinline__ void ldsm4(uint32_t* r, uint32_t addr) {
    asm volatile("ldmatrix.sync.aligned.m8n8.x4.shared.b16 {%0,%1,%2,%3}, [%4];"
        : "=r"(r[0]), "=r"(r[1]), "=r"(r[2]), "=r"(r[3]) : "r"(addr));
}
__device__ __forceinline__ void mma_bf16(float* c, const uint32_t* a, const uint32_t* b) {
    asm volatile("mma.sync.aligned.m16n8k16.row.col.f32.bf16.bf16.f32 "
        "{%0,%1,%2,%3}, {%4,%5,%6,%7}, {%8,%9}, {%0,%1,%2,%3};"
        : "+f"(c[0]), "+f"(c[1]), "+f"(c[2]), "+f"(c[3])
        : "r"(a[0]), "r"(a[1]), "r"(a[2]), "r"(a[3]), "r"(b[0]), "r"(b[1]));
}
__device__ __forceinline__ void mma_f16(float* c, const uint32_t* a, const uint32_t* b) {
    asm volatile("mma.sync.aligned.m16n8k16.row.col.f32.f16.f16.f32 "
        "{%0,%1,%2,%3}, {%4,%5,%6,%7}, {%8,%9}, {%0,%1,%2,%3};"
        : "+f"(c[0]), "+f"(c[1]), "+f"(c[2]), "+f"(c[3])
        : "r"(a[0]), "r"(a[1]), "r"(a[2]), "r"(a[3]), "r"(b[0]), "r"(b[1]));
}

// ================= GEMM1: bf16 3-term split, relu, fp16 out ====================
#define MAT_BYTES 10240            // 128*40*2
#define STAGE_BYTES (4*MAT_BYTES)  // 40960
#define NSTAGE 3

__device__ __forceinline__ void load_stage(
    uint32_t sb, const __nv_bfloat16* Ah, const __nv_bfloat16* Al,
    const __nv_bfloat16* Bh, const __nv_bfloat16* Bl,
    size_t m0, size_t n0, int k0, int lda, int ldb, int t)
{
    const __nv_bfloat16* srcs[4] = { Ah, Al, Bh, Bl };
    #pragma unroll
    for (int p = 0; p < 8; p++) {
        int idx = t + p * 256;           // 0..2047
        int mat = idx >> 9;              // 0..3
        int r   = (idx & 511) >> 2;      // 0..127
        int ch  = idx & 3;               // 16B chunk in row
        size_t grow = (mat < 2 ? m0 : n0) + r;
        int ld = (mat < 2 ? lda : ldb);
        const __nv_bfloat16* src = srcs[mat] + grow * (size_t)ld + k0 + ch * 8;
        cp16(sb + mat * MAT_BYTES + r * 80 + ch * 16, src);
    }
}

__global__ void __launch_bounds__(256) gemm1_kernel(
    const __nv_bfloat16* __restrict__ Ah, const __nv_bfloat16* __restrict__ Al,
    const __nv_bfloat16* __restrict__ Bh, const __nv_bfloat16* __restrict__ Bl,
    const float* __restrict__ bias, __half* __restrict__ outh,
    int K, int lda, int ldb, int tiles_n, int ldo)
{
    extern __shared__ char smem[];
    uint32_t sbase = smem_u32(smem);
    const int t = threadIdx.x;
    const int wid = t >> 5, lane = t & 31;
    const int warp_m = wid & 1, warp_n = wid >> 1;   // 2x4 warps, warp tile 64x32

    const int G = 8;
    int idx = blockIdx.x;
    int band = idx / (G * tiles_n);
    int r = idx % (G * tiles_n);
    size_t m0 = (size_t)(band * G + (r % G)) * 128;
    size_t n0 = (size_t)(r / G) * 128;

    float acc[4][4][4];
    #pragma unroll
    for (int i = 0; i < 4; i++)
        #pragma unroll
        for (int j = 0; j < 4; j++)
            #pragma unroll
            for (int e = 0; e < 4; e++) acc[i][j][e] = 0.0f;

    const int C = K >> 5;   // K chunks of 32
    load_stage(sbase + 0 * STAGE_BYTES, Ah, Al, Bh, Bl, m0, n0, 0,  lda, ldb, t); cp_commit();
    load_stage(sbase + 1 * STAGE_BYTES, Ah, Al, Bh, Bl, m0, n0, 32, lda, ldb, t); cp_commit();

    const int lrow = lane & 15;
    const int lcolb = (lane >> 4) * 16;

    for (int c = 0; c < C; c++) {
        cp_wait1();
        __syncthreads();
        if (c + 2 < C)
            load_stage(sbase + ((c + 2) % NSTAGE) * STAGE_BYTES,
                       Ah, Al, Bh, Bl, m0, n0, (c + 2) * 32, lda, ldb, t);
        cp_commit();

        uint32_t sb = sbase + (c % NSTAGE) * STAGE_BYTES;
        uint32_t aBaseH = sb +                (warp_m * 64 + lrow) * 80;
        uint32_t aBaseL = sb + MAT_BYTES    + (warp_m * 64 + lrow) * 80;
        uint32_t bBaseH = sb + 2*MAT_BYTES  + (warp_n * 32 + lrow) * 80;
        uint32_t bBaseL = sb + 3*MAT_BYTES  + (warp_n * 32 + lrow) * 80;

        #pragma unroll
        for (int ks = 0; ks < 2; ks++) {
            int kb = ks * 32 + lcolb;
            uint32_t ah[4][4], al[4][4], bh[4][2], bl[4][2];
            #pragma unroll
            for (int fm = 0; fm < 4; fm++) {
                ldsm4(ah[fm], aBaseH + fm * 16 * 80 + kb);
                ldsm4(al[fm], aBaseL + fm * 16 * 80 + kb);
            }
            #pragma unroll
            for (int fp = 0; fp < 2; fp++) {
                uint32_t rr[4];
                ldsm4(rr, bBaseH + fp * 16 * 80 + kb);
                bh[fp*2][0] = rr[0]; bh[fp*2][1] = rr[2];
                bh[fp*2+1][0] = rr[1]; bh[fp*2+1][1] = rr[3];
                ldsm4(rr, bBaseL + fp * 16 * 80 + kb);
                bl[fp*2][0] = rr[0]; bl[fp*2][1] = rr[2];
                bl[fp*2+1][0] = rr[1]; bl[fp*2+1][1] = rr[3];
            }
            #pragma unroll
            for (int fm = 0; fm < 4; fm++)
                #pragma unroll
                for (int fn = 0; fn < 4; fn++) {
                    mma_bf16(acc[fm][fn], ah[fm], bh[fn]);
                    mma_bf16(acc[fm][fn], al[fm], bh[fn]);
                    mma_bf16(acc[fm][fn], ah[fm], bl[fn]);
                }
        }
        __syncthreads();
    }

    // epilogue: relu -> fp16 store
    const int g = lane >> 2;
    const int cq = (lane & 3) * 2;
    #pragma unroll
    for (int fm = 0; fm < 4; fm++) {
        #pragma unroll
        for (int fn = 0; fn < 4; fn++) {
            int colbase = (int)n0 + warp_n * 32 + fn * 8 + cq;
            float b0 = bias[colbase], b1 = bias[colbase + 1];
            #pragma unroll
            for (int hrow = 0; hrow < 2; hrow++) {
                size_t row = m0 + warp_m * 64 + fm * 16 + g + hrow * 8;
                float v0 = fmaxf(acc[fm][fn][hrow * 2 + 0] + b0, 0.0f);
                float v1 = fmaxf(acc[fm][fn][hrow * 2 + 1] + b1, 0.0f);
                __half2 hv;
                hv.x = __float2half(v0);
                hv.y = __float2half(v1);
                *reinterpret_cast<__half2*>(&outh[row * (size_t)ldo + colbase]) = hv;
            }
        }
    }
}

// ================= GEMM2: single fp16 HMMA =================
#define FMAT 10240                 // 128*40*2
#define FSTAGE (2*FMAT)            // 20480
#define FNSTAGE 3

__device__ __forceinline__ void load_stage_f16(
    uint32_t sb, const __half* A, const __half* B,
    size_t m0, size_t n0, int k0, int ld, int t)
{
    const __half* srcs[2] = { A, B };
    #pragma unroll
    for (int p = 0; p < 4; p++) {
        int idx = t + p * 256;        // 0..1023
        int mat = idx >> 9;           // 0..1
        int r   = (idx & 511) >> 2;   // 0..127
        int ch  = idx & 3;
        size_t grow = (mat == 0 ? m0 : n0) + r;
        cp16(sb + mat * FMAT + r * 80 + ch * 16,
             srcs[mat] + grow * (size_t)ld + k0 + ch * 8);
    }
}

__global__ void __launch_bounds__(256) gemm2_kernel(
    const __half* __restrict__ A, const __half* __restrict__ B,
    const float* __restrict__ bias, float* __restrict__ outf,
    int K, int ld, int tiles_n, int Nreal, int ldo)
{
    extern __shared__ char smem[];
    uint32_t sbase = smem_u32(smem);
    const int t = threadIdx.x;
    const int wid = t >> 5, lane = t & 31;
    const int warp_m = wid & 1, warp_n = wid >> 1;

    const int G = 8;
    int idx = blockIdx.x;
    int band = idx / (G * tiles_n);
    int r = idx % (G * tiles_n);
    size_t m0 = (size_t)(band * G + (r % G)) * 128;
    size_t n0 = (size_t)(r / G) * 128;

    float acc[4][4][4];
    #pragma unroll
    for (int i = 0; i < 4; i++)
        #pragma unroll
        for (int j = 0; j < 4; j++)
            #pragma unroll
            for (int e = 0; e < 4; e++) acc[i][j][e] = 0.0f;

    const int C = K >> 5;
    load_stage_f16(sbase + 0 * FSTAGE, A, B, m0, n0, 0,  ld, t); cp_commit();
    load_stage_f16(sbase + 1 * FSTAGE, A, B, m0, n0, 32, ld, t); cp_commit();

    const int lrow = lane & 15;
    const int lcolb = (lane >> 4) * 16;

    for (int c = 0; c < C; c++) {
        cp_wait1();
        __syncthreads();
        if (c + 2 < C)
            load_stage_f16(sbase + ((c + 2) % FNSTAGE) * FSTAGE,
                           A, B, m0, n0, (c + 2) * 32, ld, t);
        cp_commit();

        uint32_t sb = sbase + (c % FNSTAGE) * FSTAGE;
        uint32_t aBase = sb +        (warp_m * 64 + lrow) * 80;
        uint32_t bBase = sb + FMAT + (warp_n * 32 + lrow) * 80;

        #pragma unroll
        for (int ks = 0; ks < 2; ks++) {
            int kb = ks * 32 + lcolb;
            uint32_t af[4][4], bf[4][2];
            #pragma unroll
            for (int fm = 0; fm < 4; fm++)
                ldsm4(af[fm], aBase + fm * 16 * 80 + kb);
            #pragma unroll
            for (int fp = 0; fp < 2; fp++) {
                uint32_t rr[4];
                ldsm4(rr, bBase + fp * 16 * 80 + kb);
                bf[fp*2][0] = rr[0]; bf[fp*2][1] = rr[2];
                bf[fp*2+1][0] = rr[1]; bf[fp*2+1][1] = rr[3];
            }
            #pragma unroll
            for (int fm = 0; fm < 4; fm++)
                #pragma unroll
                for (int fn = 0; fn < 4; fn++)
                    mma_f16(acc[fm][fn], af[fm], bf[fn]);
        }
        __syncthreads();
    }

    const int g = lane >> 2;
    const int cq = (lane & 3) * 2;
    #pragma unroll
    for (int fm = 0; fm < 4; fm++) {
        #pragma unroll
        for (int fn = 0; fn < 4; fn++) {
            int colbase = (int)n0 + warp_n * 32 + fn * 8 + cq;
            if (colbase < Nreal) {
                float b0 = bias[colbase], b1 = bias[colbase + 1];
                #pragma unroll
                for (int hrow = 0; hrow < 2; hrow++) {
                    size_t row = m0 + warp_m * 64 + fm * 16 + g + hrow * 8;
                    float2 fv;
                    fv.x = acc[fm][fn][hrow * 2 + 0] + b0;
                    fv.y = acc[fm][fn][hrow * 2 + 1] + b1;
                    *reinterpret_cast<float2*>(&outf[row * (size_t)ldo + colbase]) = fv;
                }
            }
        }
    }
}

// ---------------- fp32 -> bf16 hi/lo split (elementwise) ----------------
__global__ __launch_bounds__(256) void split_kernel(
    const float* __restrict__ in, __nv_bfloat16* __restrict__ oh,
    __nv_bfloat16* __restrict__ ol, int count)
{
    int i = blockIdx.x * 256 + threadIdx.x;
    if (i < count) {
        float v = in[i];
        __nv_bfloat16 h = __float2bfloat16(v);
        oh[i] = h;
        ol[i] = __float2bfloat16(v - __bfloat162float(h));
    }
}

// ---------------- transpose + split: fp32 [K,N] -> bf16 [N,K] hi/lo ----------------
__global__ __launch_bounds__(256) void transpose_split_kernel(
    const float* __restrict__ in, __nv_bfloat16* __restrict__ oh,
    __nv_bfloat16* __restrict__ ol, int K, int N)
{
    __shared__ float tile[32][33];
    int n0 = blockIdx.x * 32, k0 = blockIdx.y * 32;
    int tx = threadIdx.x & 31, ty = threadIdx.x >> 5;
    #pragma unroll
    for (int j = 0; j < 4; j++) {
        int kk = k0 + ty + j * 8;
        int nn = n0 + tx;
        tile[ty + j * 8][tx] = (nn < N) ? in[(size_t)kk * N + nn] : 0.0f;
    }
    __syncthreads();
    #pragma unroll
    for (int j = 0; j < 4; j++) {
        int nn = n0 + ty + j * 8;
        int kk = k0 + tx;
        float v = tile[tx][ty + j * 8];
        __nv_bfloat16 h = __float2bfloat16(v);
        oh[(size_t)nn * K + kk] = h;
        ol[(size_t)nn * K + kk] = __float2bfloat16(v - __bfloat162float(h));
    }
}

// ---------------- transpose to fp16: fp32 [K,N] -> fp16 [Npad,K] ----------------
__global__ __launch_bounds__(256) void transpose_half_kernel(
    const float* __restrict__ in, __half* __restrict__ out, int K, int N)
{
    __shared__ float tile[32][33];
    int n0 = blockIdx.x * 32, k0 = blockIdx.y * 32;
    int tx = threadIdx.x & 31, ty = threadIdx.x >> 5;
    #pragma unroll
    for (int j = 0; j < 4; j++) {
        int kk = k0 + ty + j * 8;
        int nn = n0 + tx;
        tile[ty + j * 8][tx] = (nn < N) ? in[(size_t)kk * N + nn] : 0.0f;
    }
    __syncthreads();
    #pragma unroll
    for (int j = 0; j < 4; j++) {
        int nn = n0 + ty + j * 8;
        int kk = k0 + tx;
        out[(size_t)nn * K + kk] = __float2half(tile[tx][ty + j * 8]);
    }
}

// ---------------- embedding + positional encoding ----------------
__global__ __launch_bounds__(256) void embed_kernel(
    const int* __restrict__ ids, const float* __restrict__ emb, float* __restrict__ out)
{
    int bs = blockIdx.x;
    int s  = bs & (Ss - 1);
    int id = ids[bs];
    const float* erow = emb + (size_t)id * Ee;
    float* orow = out + (size_t)bs * Ee;
    for (int e = threadIdx.x; e < Ee; e += blockDim.x) {
        int i = e & 255;
        float rate = expf(-(float)i * (9.210340371976184f / 256.0f));
        float ang = (float)s * rate;
        float p = (e < 256) ? sinf(ang) : cosf(ang);
        orow[e] = erow[e] * SQRT_E + p;
    }
}

// ---------------- repack [H,E,HD] -> [E, H*HD] ----------------
__global__ __launch_bounds__(256) void repack_kernel(
    const float* __restrict__ w, float* __restrict__ out)
{
    int e = blockIdx.x;
    for (int j = threadIdx.x; j < Ee; j += blockDim.x)
        out[e * Ee + j] = w[(j >> 6) * (Ee * HDm) + e * HDm + (j & 63)];
}

// ---------------- fp32 tiled SGEMM (E-size ops) ----------------
__global__ __launch_bounds__(256) void sgemm_kernel(
    const float* __restrict__ A, const float* __restrict__ B,
    const float* __restrict__ bias, float* __restrict__ C,
    int M, int N, int K, int relu)
{
    __shared__ float As[16][128];
    __shared__ float Bs[16][128];
    const int t  = threadIdx.x;
    const int tx = t & 15, ty = t >> 4;
    const int row0 = blockIdx.y * 128, col0 = blockIdx.x * 128;
    const int aRow = t >> 2, aCol = (t & 3) * 4;
    const int bRow = t >> 5, bCol = (t & 31) * 4;

    float acc[8][8];
    #pragma unroll
    for (int i = 0; i < 8; i++)
        #pragma unroll
        for (int j = 0; j < 8; j++) acc[i][j] = 0.0f;

    for (int k0 = 0; k0 < K; k0 += 16) {
        #pragma unroll
        for (int p = 0; p < 2; p++) {
            int m = aRow + p * 64;
            float4 vA = *reinterpret_cast<const float4*>(&A[(size_t)(row0 + m) * K + k0 + aCol]);
            As[aCol + 0][m] = vA.x; As[aCol + 1][m] = vA.y;
            As[aCol + 2][m] = vA.z; As[aCol + 3][m] = vA.w;
        }
        #pragma unroll
        for (int p = 0; p < 2; p++) {
            int kk = bRow + p * 8;
            int c = col0 + bCol;
            float4 vB = make_float4(0.f, 0.f, 0.f, 0.f);
            if (c < N) vB = *reinterpret_cast<const float4*>(&B[(size_t)(k0 + kk) * N + c]);
            *reinterpret_cast<float4*>(&Bs[kk][bCol]) = vB;
        }
        __syncthreads();
        #pragma unroll
        for (int kk = 0; kk < 16; kk++) {
            float ra[8], rb[8];
            float4 a0 = *reinterpret_cast<const float4*>(&As[kk][ty * 8]);
            float4 a1 = *reinterpret_cast<const float4*>(&As[kk][ty * 8 + 4]);
            float4 b0 = *reinterpret_cast<const float4*>(&Bs[kk][tx * 8]);
            float4 b1 = *reinterpret_cast<const float4*>(&Bs[kk][tx * 8 + 4]);
            ra[0]=a0.x; ra[1]=a0.y; ra[2]=a0.z; ra[3]=a0.w;
            ra[4]=a1.x; ra[5]=a1.y; ra[6]=a1.z; ra[7]=a1.w;
            rb[0]=b0.x; rb[1]=b0.y; rb[2]=b0.z; rb[3]=b0.w;
            rb[4]=b1.x; rb[5]=b1.y; rb[6]=b1.z; rb[7]=b1.w;
            #pragma unroll
            for (int i = 0; i < 8; i++)
                #pragma unroll
                for (int j = 0; j < 8; j++)
                    acc[i][j] += ra[i] * rb[j];
        }
        __syncthreads();
    }
    #pragma unroll
    for (int i = 0; i < 8; i++) {
        int m = row0 + ty * 8 + i;
        #pragma unroll
        for (int j = 0; j < 8; j++) {
            int c = col0 + tx * 8 + j;
            if (c < N) {
                float val = acc[i][j];
                if (bias) val += bias[c];
                if (relu) val = fmaxf(val, 0.0f);
                C[(size_t)m * N + c] = val;
            }
        }
    }
}

// ---------------- QK^T + scale + causal ----------------
__global__ __launch_bounds__(256) void qk_kernel(
    const float* __restrict__ Q, const float* __restrict__ Km,
    float* __restrict__ L, int causal)
{
    __shared__ float Qs[64][68];
    __shared__ float Ks[64][68];
    int bh = blockIdx.z, b = bh >> 3, h = bh & 7;
    int q0 = blockIdx.y * 64, k0 = blockIdx.x * 64;
    int t = threadIdx.x;
    #pragma unroll
    for (int p = 0; p < 4; p++) {
        int idx = t + p * 256;
        int r = idx >> 4, f4 = (idx & 15) * 4;
        *reinterpret_cast<float4*>(&Qs[r][f4]) =
            *reinterpret_cast<const float4*>(&Q[(size_t)(b * Ss + q0 + r) * Ee + h * HDm + f4]);
        *reinterpret_cast<float4*>(&Ks[r][f4]) =
            *reinterpret_cast<const float4*>(&Km[(size_t)(b * Ss + k0 + r) * Ee + h * HDm + f4]);
    }
    __syncthreads();
    int tx = t & 15, ty = t >> 4;
    float acc[4][4] = {};
    #pragma unroll 4
    for (int d = 0; d < 64; d++) {
        float ra[4], rb[4];
        #pragma unroll
        for (int i = 0; i < 4; i++) ra[i] = Qs[ty * 4 + i][d];
        #pragma unroll
        for (int j = 0; j < 4; j++) rb[j] = Ks[tx * 4 + j][d];
        #pragma unroll
        for (int i = 0; i < 4; i++)
            #pragma unroll
            for (int j = 0; j < 4; j++)
                acc[i][j] += ra[i] * rb[j];
    }
    #pragma unroll
    for (int i = 0; i < 4; i++) {
        int qi = q0 + ty * 4 + i;
        #pragma unroll
        for (int j = 0; j < 4; j++) {
            int ki = k0 + tx * 4 + j;
            float v = acc[i][j] * QK_SCALE;
            if (causal && ki > qi) v = -INFINITY;
            L[((size_t)bh * Ss + qi) * Ss + ki] = v;
        }
    }
}

// ---------------- row softmax ----------------
__global__ __launch_bounds__(256) void softmax_kernel(float* __restrict__ L)
{
    __shared__ float red[256];
    float* row = L + (size_t)blockIdx.x * Ss;
    int t = threadIdx.x;
    float a = row[t], b = row[t + 256];
    red[t] = fmaxf(a, b);
    __syncthreads();
    for (int s = 128; s > 0; s >>= 1) { if (t < s) red[t] = fmaxf(red[t], red[t + s]); __syncthreads(); }
    float m = red[0];
    __syncthreads();
    float e0 = expf(a - m), e1 = expf(b - m);
    red[t] = e0 + e1;
    __syncthreads();
    for (int s = 128; s > 0; s >>= 1) { if (t < s) red[t] += red[t + s]; __syncthreads(); }
    float inv = 1.0f / red[0];
    row[t] = e0 * inv;
    row[t + 256] = e1 * inv;
}

// ---------------- P @ V ----------------
__global__ __launch_bounds__(256) void pv_kernel(
    const float* __restrict__ P, const float* __restrict__ V, float* __restrict__ O)
{
    __shared__ float Ps[64][68];
    __shared__ float Vs[64][68];
    int bh = blockIdx.y, b = bh >> 3, h = bh & 7;
    int q0 = blockIdx.x * 64;
    int t = threadIdx.x, tx = t & 15, ty = t >> 4;
    float acc[4][4] = {};
    for (int k0 = 0; k0 < Ss; k0 += 64) {
        #pragma unroll
        for (int p = 0; p < 4; p++) {
            int idx = t + p * 256;
            int r = idx >> 4, f4 = (idx & 15) * 4;
            *reinterpret_cast<float4*>(&Ps[r][f4]) =
                *reinterpret_cast<const float4*>(&P[((size_t)bh * Ss + q0 + r) * Ss + k0 + f4]);
            *reinterpret_cast<float4*>(&Vs[r][f4]) =
                *reinterpret_cast<const float4*>(&V[(size_t)(b * Ss + k0 + r) * Ee + h * HDm + f4]);
        }
        __syncthreads();
        #pragma unroll 4
        for (int kk = 0; kk < 64; kk++) {
            float ra[4], rb[4];
            #pragma unroll
            for (int i = 0; i < 4; i++) ra[i] = Ps[ty * 4 + i][kk];
            #pragma unroll
            for (int j = 0; j < 4; j++) rb[j] = Vs[kk][tx * 4 + j];
            #pragma unroll
            for (int i = 0; i < 4; i++)
                #pragma unroll
                for (int j = 0; j < 4; j++)
                    acc[i][j] += ra[i] * rb[j];
        }
        __syncthreads();
    }
    #pragma unroll
    for (int i = 0; i < 4; i++)
        #pragma unroll
        for (int j = 0; j < 4; j++)
            O[(size_t)(b * Ss + q0 + ty * 4 + i) * Ee + h * HDm + tx * 4 + j] = acc[i][j];
}

// ---------------- LN(A + R)*g + b (opt relu) ----------------
__global__ __launch_bounds__(256) void ln_kernel(
    const float* __restrict__ A, const float* __restrict__ R,
    const float* __restrict__ g, const float* __restrict__ be,
    float* __restrict__ out, int relu)
{
    __shared__ float red[256];
    size_t row = blockIdx.x;
    int t = threadIdx.x;
    float a0 = A[row * Ee + t] + R[row * Ee + t];
    float a1 = A[row * Ee + t + 256] + R[row * Ee + t + 256];
    red[t] = a0 + a1;
    __syncthreads();
    for (int s = 128; s > 0; s >>= 1) { if (t < s) red[t] += red[t + s]; __syncthreads(); }
    float mean = red[0] * (1.0f / Ee);
    __syncthreads();
    float d0 = a0 - mean, d1 = a1 - mean;
    red[t] = d0 * d0 + d1 * d1;
    __syncthreads();
    for (int s = 128; s > 0; s >>= 1) { if (t < s) red[t] += red[t + s]; __syncthreads(); }
    float var = red[0] * (1.0f / Ee);
    float inv = rsqrtf(var + LN_EPS);
    float v0 = d0 * inv * g[t] + be[t];
    float v1 = d1 * inv * g[t + 256] + be[t + 256];
    if (relu) { v0 = fmaxf(v0, 0.0f); v1 = fmaxf(v1, 0.0f); }
    out[row * Ee + t] = v0;
    out[row * Ee + t + 256] = v1;
}

// ---------------- host orchestration ----------------
static inline void launch_gemm(const float* A, const float* B, const float* bias,
                               float* C, int M, int N, int K, int relu)
{
    dim3 grid((N + 127) / 128, M / 128);
    sgemm_kernel<<<grid, 256>>>(A, B, bias, C, M, N, K, relu);
}

extern "C" void kernel_launch(void* const* d_in, const int* in_sizes, int n_in,
                              void* d_out, int out_size)
{
    const int*   src_ids  = (const int*)  d_in[0];
    const int*   tgt_ids  = (const int*)  d_in[1];
    const float* src_emb  = (const float*)d_in[2];
    const float* tgt_emb  = (const float*)d_in[3];
    const float* enc_wk   = (const float*)d_in[4];
    const float* enc_wv   = (const float*)d_in[5];
    const float* enc_wq   = (const float*)d_in[6];
    const float* enc_dw   = (const float*)d_in[7];
    const float* enc_db   = (const float*)d_in[8];
    const float* enc_ffw  = (const float*)d_in[9];
    const float* enc_ffb  = (const float*)d_in[10];
    const float* enc_ln_g = (const float*)d_in[11];
    const float* enc_ln_b = (const float*)d_in[12];
    const float* dec_swk  = (const float*)d_in[13];
    const float* dec_swv  = (const float*)d_in[14];
    const float* dec_swq  = (const float*)d_in[15];
    const float* dec_sdw  = (const float*)d_in[16];
    const float* dec_sdb  = (const float*)d_in[17];
    const float* dec_cwk  = (const float*)d_in[18];
    const float* dec_cwv  = (const float*)d_in[19];
    const float* dec_cwq  = (const float*)d_in[20];
    const float* dec_cdw  = (const float*)d_in[21];
    const float* dec_cdb  = (const float*)d_in[22];
    const float* dec_ffw  = (const float*)d_in[23];
    const float* dec_ffb  = (const float*)d_in[24];
    const float* dec_ln_g = (const float*)d_in[25];
    const float* dec_ln_b = (const float*)d_in[26];
    const float* cls_w1   = (const float*)d_in[27];
    const float* cls_b1   = (const float*)d_in[28];
    const float* cls_w2   = (const float*)d_in[29];
    const float* cls_b2   = (const float*)d_in[30];

    float *x, *y, *q, *k, *v, *att, *t0, *t1, *t2, *w, *logits;
    __nv_bfloat16 *A1h, *A1l, *B1h, *B1l;
    __half *A2, *B2;
    cudaGetSymbolAddress((void**)&x,      g_x);
    cudaGetSymbolAddress((void**)&y,      g_y);
    cudaGetSymbolAddress((void**)&q,      g_q);
    cudaGetSymbolAddress((void**)&k,      g_k);
    cudaGetSymbolAddress((void**)&v,      g_v);
    cudaGetSymbolAddress((void**)&att,    g_att);
    cudaGetSymbolAddress((void**)&t0,     g_t0);
    cudaGetSymbolAddress((void**)&t1,     g_t1);
    cudaGetSymbolAddress((void**)&t2,     g_t2);
    cudaGetSymbolAddress((void**)&w,      g_w);
    cudaGetSymbolAddress((void**)&logits, g_logits);
    cudaGetSymbolAddress((void**)&A1h, g_A1h);
    cudaGetSymbolAddress((void**)&A1l, g_A1l);
    cudaGetSymbolAddress((void**)&B1h, g_B1h);
    cudaGetSymbolAddress((void**)&B1l, g_B1l);
    cudaGetSymbolAddress((void**)&A2,  g_A2);
    cudaGetSymbolAddress((void**)&B2,  g_B2);

    static bool attr_set = false;
    if (!attr_set) {
        cudaFuncSetAttribute(gemm1_kernel, cudaFuncAttributeMaxDynamicSharedMemorySize,
                             NSTAGE * STAGE_BYTES);
        cudaFuncSetAttribute(gemm2_kernel, cudaFuncAttributeMaxDynamicSharedMemorySize,
                             FNSTAGE * FSTAGE);
        attr_set = true;
    }

    // weight prep (independent of activations)
    transpose_split_kernel<<<dim3(CLS_H / 32, Ee / 32), 256>>>(cls_w1, B1h, B1l, Ee, CLS_H);
    transpose_half_kernel<<<dim3(VOC_PAD / 32, CLS_H / 32), 256>>>(cls_w2, B2, CLS_H, VOC);

    // embeddings + positional encoding
    embed_kernel<<<ROWS, 256>>>(src_ids, src_emb, x);
    embed_kernel<<<ROWS, 256>>>(tgt_ids, tgt_emb, y);

    #define RUN_MHA(Xk, Xv, Xq, wk_, wv_, wq_, dw_, db_, OUT, CAUSAL)              \
        do {                                                                       \
            repack_kernel<<<Ee, 256>>>((wq_), w);                                  \
            launch_gemm((Xq), w, nullptr, q, ROWS, Ee, Ee, 0);                     \
            repack_kernel<<<Ee, 256>>>((wk_), w);                                  \
            launch_gemm((Xk), w, nullptr, k, ROWS, Ee, Ee, 0);                     \
            repack_kernel<<<Ee, 256>>>((wv_), w);                                  \
            launch_gemm((Xv), w, nullptr, v, ROWS, Ee, Ee, 0);                     \
            qk_kernel<<<dim3(8, 8, Bb * NH), 256>>>(q, k, logits, (CAUSAL));       \
            softmax_kernel<<<Bb * NH * Ss, 256>>>(logits);                         \
            pv_kernel<<<dim3(8, Bb * NH), 256>>>(logits, v, att);                  \
            launch_gemm(att, (dw_), (db_), (OUT), ROWS, Ee, Ee, 0);                \
        } while (0)

    // ---- encoder ----
    RUN_MHA(x, x, x, enc_wk, enc_wv, enc_wq, enc_dw, enc_db, t0, 1);
    ln_kernel<<<ROWS, 256>>>(x, t0, enc_ln_g, enc_ln_b, t1, 0);
    launch_gemm(t1, enc_ffw, enc_ffb, t2, ROWS, Ee, Ee, 0);
    ln_kernel<<<ROWS, 256>>>(t1, t2, enc_ln_g, enc_ln_b, x, 0);

    // ---- decoder ----
    RUN_MHA(y, y, y, dec_swk, dec_swv, dec_swq, dec_sdw, dec_sdb, t0, 1);
    ln_kernel<<<ROWS, 256>>>(t0, y, dec_ln_g, dec_ln_b, t1, 0);
    RUN_MHA(x, x, t1, dec_cwk, dec_cwv, dec_cwq, dec_cdw, dec_cdb, t0, 0);
    ln_kernel<<<ROWS, 256>>>(t0, t1, dec_ln_g, dec_ln_b, t2, 0);
    launch_gemm(t2, dec_ffw, dec_ffb, t0, ROWS, Ee, Ee, 0);
    ln_kernel<<<ROWS, 256>>>(t0, t2, dec_ln_g, dec_ln_b, t1, 1);  // dec_out

    // ---- classifier GEMM1 (bf16 3-term split): hid = relu(dec_out@w1 + b1) -> fp16
    split_kernel<<<(ROWS * Ee + 255) / 256, 256>>>(t1, A1h, A1l, ROWS * Ee);
    gemm1_kernel<<<(ROWS / 128) * (CLS_H / 128), 256, NSTAGE * STAGE_BYTES>>>(
        A1h, A1l, B1h, B1l, cls_b1, A2,
        Ee, Ee, Ee, CLS_H / 128, CLS_H);

    // ---- classifier GEMM2 (single fp16): out = hid@w2 + b2
    gemm2_kernel<<<(ROWS / 128) * (VOC_PAD / 128), 256, FNSTAGE * FSTAGE>>>(
        A2, B2, cls_b2, (float*)d_out,
        CLS_H, CLS_H, VOC_PAD / 128, VOC, VOC);
}

// round 14
// speedup vs baseline: 4.8218x; 1.0857x over previous
#include <cuda_runtime.h>
#include <cuda_bf16.h>
#include <cuda_fp16.h>
#include <math.h>
#include <stdint.h>

// Problem dims
#define Bb 8
#define Ss 512
#define Ee 512
#define NH 8
#define HDm 64
#define ROWS (Bb*Ss)        // 4096 token rows
#define CLS_H 16000
#define VOC 8000
#define VOC_PAD 8064
#define SQRT_E 22.627416997969522f
#define QK_SCALE 0.04419417382415922f   // 1/sqrt(512)
#define LN_EPS 1e-3f

// ---------------- scratch (device globals; no allocations allowed) -------------
__device__ float g_x[ROWS*Ee];
__device__ float g_y[ROWS*Ee];
__device__ float g_q[ROWS*Ee];
__device__ float g_k[ROWS*Ee];
__device__ float g_v[ROWS*Ee];
__device__ float g_att[ROWS*Ee];
__device__ float g_t0[ROWS*Ee];
__device__ float g_t1[ROWS*Ee];
__device__ float g_t2[ROWS*Ee];
__device__ float g_w[Ee*Ee];
__device__ float g_logits[Bb*NH*Ss*Ss];

// classifier fp16 buffers
__device__ __half g_A1[ROWS*Ee];               // dec_out fp16 [4096,512]
__device__ __half g_B1[(size_t)CLS_H*Ee];      // w1^T fp16 [16000,512]
__device__ __half g_A2[(size_t)ROWS*CLS_H];    // hidden fp16 [4096,16000]
__device__ __half g_B2[(size_t)VOC_PAD*CLS_H]; // w2^T fp16 padded [8064,16000]

// ================= helpers =================
__device__ __forceinline__ uint32_t smem_u32(const void* p) {
    uint32_t a;
    asm("{ .reg .u64 t; cvta.to.shared.u64 t, %1; cvt.u32.u64 %0, t; }" : "=r"(a) : "l"(p));
    return a;
}
__device__ __forceinline__ void cp16(uint32_t dst, const void* src) {
    asm volatile("cp.async.cg.shared.global [%0], [%1], 16;" :: "r"(dst), "l"(src));
}
__device__ __forceinline__ void cp_commit() { asm volatile("cp.async.commit_group;"); }
__device__ __forceinline__ void cp_wait1()  { asm volatile("cp.async.wait_group 1;"); }

__device__ __forceinline__ void ldsm4(uint32_t* r, uint32_t addr) {
    asm volatile("ldmatrix.sync.aligned.m8n8.x4.shared.b16 {%0,%1,%2,%3}, [%4];"
        : "=r"(r[0]), "=r"(r[1]), "=r"(r[2]), "=r"(r[3]) : "r"(addr));
}
__device__ __forceinline__ void mma_f16(float* c, const uint32_t* a, const uint32_t* b) {
    asm volatile("mma.sync.aligned.m16n8k16.row.col.f32.f16.f16.f32 "
        "{%0,%1,%2,%3}, {%4,%5,%6,%7}, {%8,%9}, {%0,%1,%2,%3};"
        : "+f"(c[0]), "+f"(c[1]), "+f"(c[2]), "+f"(c[3])
        : "r"(a[0]), "r"(a[1]), "r"(a[2]), "r"(a[3]), "r"(b[0]), "r"(b[1]));
}

// ================= unified fp16 HMMA GEMM =================
// C[M,N] = A[M,K] @ B[N,K]^T + bias
// mode 0: relu -> fp16 store (outh)        (classifier GEMM1)
// mode 1: fp32 store guarded col<Nreal     (classifier GEMM2)
#define FMAT 10240                 // 128*40*2
#define FSTAGE (2*FMAT)            // 20480
#define FNSTAGE 3

__device__ __forceinline__ void load_stage_f16(
    uint32_t sb, const __half* A, const __half* B,
    size_t m0, size_t n0, int k0, int ld, int t)
{
    const __half* srcs[2] = { A, B };
    #pragma unroll
    for (int p = 0; p < 4; p++) {
        int idx = t + p * 256;        // 0..1023
        int mat = idx >> 9;           // 0..1
        int r   = (idx & 511) >> 2;   // 0..127
        int ch  = idx & 3;
        size_t grow = (mat == 0 ? m0 : n0) + r;
        cp16(sb + mat * FMAT + r * 80 + ch * 16,
             srcs[mat] + grow * (size_t)ld + k0 + ch * 8);
    }
}

__global__ void __launch_bounds__(256, 2) gemm_f16_kernel(
    const __half* __restrict__ A, const __half* __restrict__ B,
    const float* __restrict__ bias, float* __restrict__ outf,
    __half* __restrict__ outh,
    int K, int ld, int tiles_n, int Nreal, int ldo, int mode)
{
    extern __shared__ char smem[];
    uint32_t sbase = smem_u32(smem);
    const int t = threadIdx.x;
    const int wid = t >> 5, lane = t & 31;
    const int warp_m = wid & 1, warp_n = wid >> 1;   // 2x4 warps, warp tile 64x32

    const int G = 8;
    int idx = blockIdx.x;
    int band = idx / (G * tiles_n);
    int r = idx % (G * tiles_n);
    int nband = tiles_n * G;
    // last band may be partial in M when tiles_m % G != 0 (not the case here, tiles_m=32)
    size_t m0 = (size_t)(band * G + (r % G)) * 128;
    size_t n0 = (size_t)(r / G) * 128;

    float acc[4][4][4];
    #pragma unroll
    for (int i = 0; i < 4; i++)
        #pragma unroll
        for (int j = 0; j < 4; j++)
            #pragma unroll
            for (int e = 0; e < 4; e++) acc[i][j][e] = 0.0f;
    (void)nband;

    const int C = K >> 5;
    load_stage_f16(sbase + 0 * FSTAGE, A, B, m0, n0, 0,  ld, t); cp_commit();
    load_stage_f16(sbase + 1 * FSTAGE, A, B, m0, n0, 32, ld, t); cp_commit();

    const int lrow = lane & 15;
    const int lcolb = (lane >> 4) * 16;

    for (int c = 0; c < C; c++) {
        cp_wait1();
        __syncthreads();
        if (c + 2 < C)
            load_stage_f16(sbase + ((c + 2) % FNSTAGE) * FSTAGE,
                           A, B, m0, n0, (c + 2) * 32, ld, t);
        cp_commit();

        uint32_t sb = sbase + (c % FNSTAGE) * FSTAGE;
        uint32_t aBase = sb +        (warp_m * 64 + lrow) * 80;
        uint32_t bBase = sb + FMAT + (warp_n * 32 + lrow) * 80;

        #pragma unroll
        for (int ks = 0; ks < 2; ks++) {
            int kb = ks * 32 + lcolb;
            uint32_t af[4][4], bf[4][2];
            #pragma unroll
            for (int fm = 0; fm < 4; fm++)
                ldsm4(af[fm], aBase + fm * 16 * 80 + kb);
            #pragma unroll
            for (int fp = 0; fp < 2; fp++) {
                uint32_t rr[4];
                ldsm4(rr, bBase + fp * 16 * 80 + kb);
                bf[fp*2][0] = rr[0]; bf[fp*2][1] = rr[2];
                bf[fp*2+1][0] = rr[1]; bf[fp*2+1][1] = rr[3];
            }
            #pragma unroll
            for (int fm = 0; fm < 4; fm++)
                #pragma unroll
                for (int fn = 0; fn < 4; fn++)
                    mma_f16(acc[fm][fn], af[fm], bf[fn]);
        }
        __syncthreads();
    }

    const int g = lane >> 2;
    const int cq = (lane & 3) * 2;
    #pragma unroll
    for (int fm = 0; fm < 4; fm++) {
        #pragma unroll
        for (int fn = 0; fn < 4; fn++) {
            int colbase = (int)n0 + warp_n * 32 + fn * 8 + cq;
            if (mode == 0) {
                float b0 = bias[colbase], b1 = bias[colbase + 1];
                #pragma unroll
                for (int hrow = 0; hrow < 2; hrow++) {
                    size_t row = m0 + warp_m * 64 + fm * 16 + g + hrow * 8;
                    float v0 = fmaxf(acc[fm][fn][hrow * 2 + 0] + b0, 0.0f);
                    float v1 = fmaxf(acc[fm][fn][hrow * 2 + 1] + b1, 0.0f);
                    __half2 hv;
                    hv.x = __float2half(v0);
                    hv.y = __float2half(v1);
                    *reinterpret_cast<__half2*>(&outh[row * (size_t)ldo + colbase]) = hv;
                }
            } else {
                if (colbase < Nreal) {
                    float b0 = bias[colbase], b1 = bias[colbase + 1];
                    #pragma unroll
                    for (int hrow = 0; hrow < 2; hrow++) {
                        size_t row = m0 + warp_m * 64 + fm * 16 + g + hrow * 8;
                        float2 fv;
                        fv.x = acc[fm][fn][hrow * 2 + 0] + b0;
                        fv.y = acc[fm][fn][hrow * 2 + 1] + b1;
                        *reinterpret_cast<float2*>(&outf[row * (size_t)ldo + colbase]) = fv;
                    }
                }
            }
        }
    }
}

// ---------------- fp32 -> fp16 elementwise ----------------
__global__ __launch_bounds__(256) void to_half_kernel(
    const float* __restrict__ in, __half* __restrict__ out, int count)
{
    int i = (blockIdx.x * 256 + threadIdx.x) * 4;
    if (i < count) {
        float4 v = *reinterpret_cast<const float4*>(&in[i]);
        __half2 h0, h1;
        h0.x = __float2half(v.x); h0.y = __float2half(v.y);
        h1.x = __float2half(v.z); h1.y = __float2half(v.w);
        *reinterpret_cast<__half2*>(&out[i])     = h0;
        *reinterpret_cast<__half2*>(&out[i + 2]) = h1;
    }
}

// ---------------- transpose to fp16: fp32 [K,N] -> fp16 [Npad,K] ----------------
__global__ __launch_bounds__(256) void transpose_half_kernel(
    const float* __restrict__ in, __half* __restrict__ out, int K, int N)
{
    __shared__ float tile[32][33];
    int n0 = blockIdx.x * 32, k0 = blockIdx.y * 32;
    int tx = threadIdx.x & 31, ty = threadIdx.x >> 5;
    #pragma unroll
    for (int j = 0; j < 4; j++) {
        int kk = k0 + ty + j * 8;
        int nn = n0 + tx;
        tile[ty + j * 8][tx] = (nn < N) ? in[(size_t)kk * N + nn] : 0.0f;
    }
    __syncthreads();
    #pragma unroll
    for (int j = 0; j < 4; j++) {
        int nn = n0 + ty + j * 8;
        int kk = k0 + tx;
        out[(size_t)nn * K + kk] = __float2half(tile[tx][ty + j * 8]);
    }
}

// ---------------- embedding + positional encoding ----------------
__global__ __launch_bounds__(256) void embed_kernel(
    const int* __restrict__ ids, const float* __restrict__ emb, float* __restrict__ out)
{
    int bs = blockIdx.x;
    int s  = bs & (Ss - 1);
    int id = ids[bs];
    const float* erow = emb + (size_t)id * Ee;
    float* orow = out + (size_t)bs * Ee;
    for (int e = threadIdx.x; e < Ee; e += blockDim.x) {
        int i = e & 255;
        float rate = expf(-(float)i * (9.210340371976184f / 256.0f));
        float ang = (float)s * rate;
        float p = (e < 256) ? sinf(ang) : cosf(ang);
        orow[e] = erow[e] * SQRT_E + p;
    }
}

// ---------------- repack [H,E,HD] -> [E, H*HD] ----------------
__global__ __launch_bounds__(256) void repack_kernel(
    const float* __restrict__ w, float* __restrict__ out)
{
    int e = blockIdx.x;
    for (int j = threadIdx.x; j < Ee; j += blockDim.x)
        out[e * Ee + j] = w[(j >> 6) * (Ee * HDm) + e * HDm + (j & 63)];
}

// ---------------- fp32 tiled SGEMM (E-size ops) ----------------
__global__ __launch_bounds__(256) void sgemm_kernel(
    const float* __restrict__ A, const float* __restrict__ B,
    const float* __restrict__ bias, float* __restrict__ C,
    int M, int N, int K, int relu)
{
    __shared__ float As[16][128];
    __shared__ float Bs[16][128];
    const int t  = threadIdx.x;
    const int tx = t & 15, ty = t >> 4;
    const int row0 = blockIdx.y * 128, col0 = blockIdx.x * 128;
    const int aRow = t >> 2, aCol = (t & 3) * 4;
    const int bRow = t >> 5, bCol = (t & 31) * 4;

    float acc[8][8];
    #pragma unroll
    for (int i = 0; i < 8; i++)
        #pragma unroll
        for (int j = 0; j < 8; j++) acc[i][j] = 0.0f;

    for (int k0 = 0; k0 < K; k0 += 16) {
        #pragma unroll
        for (int p = 0; p < 2; p++) {
            int m = aRow + p * 64;
            float4 vA = *reinterpret_cast<const float4*>(&A[(size_t)(row0 + m) * K + k0 + aCol]);
            As[aCol + 0][m] = vA.x; As[aCol + 1][m] = vA.y;
            As[aCol + 2][m] = vA.z; As[aCol + 3][m] = vA.w;
        }
        #pragma unroll
        for (int p = 0; p < 2; p++) {
            int kk = bRow + p * 8;
            int c = col0 + bCol;
            float4 vB = make_float4(0.f, 0.f, 0.f, 0.f);
            if (c < N) vB = *reinterpret_cast<const float4*>(&B[(size_t)(k0 + kk) * N + c]);
            *reinterpret_cast<float4*>(&Bs[kk][bCol]) = vB;
        }
        __syncthreads();
        #pragma unroll
        for (int kk = 0; kk < 16; kk++) {
            float ra[8], rb[8];
            float4 a0 = *reinterpret_cast<const float4*>(&As[kk][ty * 8]);
            float4 a1 = *reinterpret_cast<const float4*>(&As[kk][ty * 8 + 4]);
            float4 b0 = *reinterpret_cast<const float4*>(&Bs[kk][tx * 8]);
            float4 b1 = *reinterpret_cast<const float4*>(&Bs[kk][tx * 8 + 4]);
            ra[0]=a0.x; ra[1]=a0.y; ra[2]=a0.z; ra[3]=a0.w;
            ra[4]=a1.x; ra[5]=a1.y; ra[6]=a1.z; ra[7]=a1.w;
            rb[0]=b0.x; rb[1]=b0.y; rb[2]=b0.z; rb[3]=b0.w;
            rb[4]=b1.x; rb[5]=b1.y; rb[6]=b1.z; rb[7]=b1.w;
            #pragma unroll
            for (int i = 0; i < 8; i++)
                #pragma unroll
                for (int j = 0; j < 8; j++)
                    acc[i][j] += ra[i] * rb[j];
        }
        __syncthreads();
    }
    #pragma unroll
    for (int i = 0; i < 8; i++) {
        int m = row0 + ty * 8 + i;
        #pragma unroll
        for (int j = 0; j < 8; j++) {
            int c = col0 + tx * 8 + j;
            if (c < N) {
                float val = acc[i][j];
                if (bias) val += bias[c];
                if (relu) val = fmaxf(val, 0.0f);
                C[(size_t)m * N + c] = val;
            }
        }
    }
}

// ---------------- QK^T + scale + causal ----------------
__global__ __launch_bounds__(256) void qk_kernel(
    const float* __restrict__ Q, const float* __restrict__ Km,
    float* __restrict__ L, int causal)
{
    __shared__ float Qs[64][68];
    __shared__ float Ks[64][68];
    int bh = blockIdx.z, b = bh >> 3, h = bh & 7;
    int q0 = blockIdx.y * 64, k0 = blockIdx.x * 64;
    int t = threadIdx.x;
    #pragma unroll
    for (int p = 0; p < 4; p++) {
        int idx = t + p * 256;
        int r = idx >> 4, f4 = (idx & 15) * 4;
        *reinterpret_cast<float4*>(&Qs[r][f4]) =
            *reinterpret_cast<const float4*>(&Q[(size_t)(b * Ss + q0 + r) * Ee + h * HDm + f4]);
        *reinterpret_cast<float4*>(&Ks[r][f4]) =
            *reinterpret_cast<const float4*>(&Km[(size_t)(b * Ss + k0 + r) * Ee + h * HDm + f4]);
    }
    __syncthreads();
    int tx = t & 15, ty = t >> 4;
    float acc[4][4] = {};
    #pragma unroll 4
    for (int d = 0; d < 64; d++) {
        float ra[4], rb[4];
        #pragma unroll
        for (int i = 0; i < 4; i++) ra[i] = Qs[ty * 4 + i][d];
        #pragma unroll
        for (int j = 0; j < 4; j++) rb[j] = Ks[tx * 4 + j][d];
        #pragma unroll
        for (int i = 0; i < 4; i++)
            #pragma unroll
            for (int j = 0; j < 4; j++)
                acc[i][j] += ra[i] * rb[j];
    }
    #pragma unroll
    for (int i = 0; i < 4; i++) {
        int qi = q0 + ty * 4 + i;
        #pragma unroll
        for (int j = 0; j < 4; j++) {
            int ki = k0 + tx * 4 + j;
            float v = acc[i][j] * QK_SCALE;
            if (causal && ki > qi) v = -INFINITY;
            L[((size_t)bh * Ss + qi) * Ss + ki] = v;
        }
    }
}

// ---------------- row softmax ----------------
__global__ __launch_bounds__(256) void softmax_kernel(float* __restrict__ L)
{
    __shared__ float red[256];
    float* row = L + (size_t)blockIdx.x * Ss;
    int t = threadIdx.x;
    float a = row[t], b = row[t + 256];
    red[t] = fmaxf(a, b);
    __syncthreads();
    for (int s = 128; s > 0; s >>= 1) { if (t < s) red[t] = fmaxf(red[t], red[t + s]); __syncthreads(); }
    float m = red[0];
    __syncthreads();
    float e0 = expf(a - m), e1 = expf(b - m);
    red[t] = e0 + e1;
    __syncthreads();
    for (int s = 128; s > 0; s >>= 1) { if (t < s) red[t] += red[t + s]; __syncthreads(); }
    float inv = 1.0f / red[0];
    row[t] = e0 * inv;
    row[t + 256] = e1 * inv;
}

// ---------------- P @ V ----------------
__global__ __launch_bounds__(256) void pv_kernel(
    const float* __restrict__ P, const float* __restrict__ V, float* __restrict__ O)
{
    __shared__ float Ps[64][68];
    __shared__ float Vs[64][68];
    int bh = blockIdx.y, b = bh >> 3, h = bh & 7;
    int q0 = blockIdx.x * 64;
    int t = threadIdx.x, tx = t & 15, ty = t >> 4;
    float acc[4][4] = {};
    for (int k0 = 0; k0 < Ss; k0 += 64) {
        #pragma unroll
        for (int p = 0; p < 4; p++) {
            int idx = t + p * 256;
            int r = idx >> 4, f4 = (idx & 15) * 4;
            *reinterpret_cast<float4*>(&Ps[r][f4]) =
                *reinterpret_cast<const float4*>(&P[((size_t)bh * Ss + q0 + r) * Ss + k0 + f4]);
            *reinterpret_cast<float4*>(&Vs[r][f4]) =
                *reinterpret_cast<const float4*>(&V[(size_t)(b * Ss + k0 + r) * Ee + h * HDm + f4]);
        }
        __syncthreads();
        #pragma unroll 4
        for (int kk = 0; kk < 64; kk++) {
            float ra[4], rb[4];
            #pragma unroll
            for (int i = 0; i < 4; i++) ra[i] = Ps[ty * 4 + i][kk];
            #pragma unroll
            for (int j = 0; j < 4; j++) rb[j] = Vs[kk][tx * 4 + j];
            #pragma unroll
            for (int i = 0; i < 4; i++)
                #pragma unroll
                for (int j = 0; j < 4; j++)
                    acc[i][j] += ra[i] * rb[j];
        }
        __syncthreads();
    }
    #pragma unroll
    for (int i = 0; i < 4; i++)
        #pragma unroll
        for (int j = 0; j < 4; j++)
            O[(size_t)(b * Ss + q0 + ty * 4 + i) * Ee + h * HDm + tx * 4 + j] = acc[i][j];
}

// ---------------- LN(A + R)*g + b (opt relu) ----------------
__global__ __launch_bounds__(256) void ln_kernel(
    const float* __restrict__ A, const float* __restrict__ R,
    const float* __restrict__ g, const float* __restrict__ be,
    float* __restrict__ out, int relu)
{
    __shared__ float red[256];
    size_t row = blockIdx.x;
    int t = threadIdx.x;
    float a0 = A[row * Ee + t] + R[row * Ee + t];
    float a1 = A[row * Ee + t + 256] + R[row * Ee + t + 256];
    red[t] = a0 + a1;
    __syncthreads();
    for (int s = 128; s > 0; s >>= 1) { if (t < s) red[t] += red[t + s]; __syncthreads(); }
    float mean = red[0] * (1.0f / Ee);
    __syncthreads();
    float d0 = a0 - mean, d1 = a1 - mean;
    red[t] = d0 * d0 + d1 * d1;
    __syncthreads();
    for (int s = 128; s > 0; s >>= 1) { if (t < s) red[t] += red[t + s]; __syncthreads(); }
    float var = red[0] * (1.0f / Ee);
    float inv = rsqrtf(var + LN_EPS);
    float v0 = d0 * inv * g[t] + be[t];
    float v1 = d1 * inv * g[t + 256] + be[t + 256];
    if (relu) { v0 = fmaxf(v0, 0.0f); v1 = fmaxf(v1, 0.0f); }
    out[row * Ee + t] = v0;
    out[row * Ee + t + 256] = v1;
}

// ---------------- host orchestration ----------------
static inline void launch_gemm(const float* A, const float* B, const float* bias,
                               float* C, int M, int N, int K, int relu)
{
    dim3 grid((N + 127) / 128, M / 128);
    sgemm_kernel<<<grid, 256>>>(A, B, bias, C, M, N, K, relu);
}

extern "C" void kernel_launch(void* const* d_in, const int* in_sizes, int n_in,
                              void* d_out, int out_size)
{
    const int*   src_ids  = (const int*)  d_in[0];
    const int*   tgt_ids  = (const int*)  d_in[1];
    const float* src_emb  = (const float*)d_in[2];
    const float* tgt_emb  = (const float*)d_in[3];
    const float* enc_wk   = (const float*)d_in[4];
    const float* enc_wv   = (const float*)d_in[5];
    const float* enc_wq   = (const float*)d_in[6];
    const float* enc_dw   = (const float*)d_in[7];
    const float* enc_db   = (const float*)d_in[8];
    const float* enc_ffw  = (const float*)d_in[9];
    const float* enc_ffb  = (const float*)d_in[10];
    const float* enc_ln_g = (const float*)d_in[11];
    const float* enc_ln_b = (const float*)d_in[12];
    const float* dec_swk  = (const float*)d_in[13];
    const float* dec_swv  = (const float*)d_in[14];
    const float* dec_swq  = (const float*)d_in[15];
    const float* dec_sdw  = (const float*)d_in[16];
    const float* dec_sdb  = (const float*)d_in[17];
    const float* dec_cwk  = (const float*)d_in[18];
    const float* dec_cwv  = (const float*)d_in[19];
    const float* dec_cwq  = (const float*)d_in[20];
    const float* dec_cdw  = (const float*)d_in[21];
    const float* dec_cdb  = (const float*)d_in[22];
    const float* dec_ffw  = (const float*)d_in[23];
    const float* dec_ffb  = (const float*)d_in[24];
    const float* dec_ln_g = (const float*)d_in[25];
    const float* dec_ln_b = (const float*)d_in[26];
    const float* cls_w1   = (const float*)d_in[27];
    const float* cls_b1   = (const float*)d_in[28];
    const float* cls_w2   = (const float*)d_in[29];
    const float* cls_b2   = (const float*)d_in[30];

    float *x, *y, *q, *k, *v, *att, *t0, *t1, *t2, *w, *logits;
    __half *A1, *B1, *A2, *B2;
    cudaGetSymbolAddress((void**)&x,      g_x);
    cudaGetSymbolAddress((void**)&y,      g_y);
    cudaGetSymbolAddress((void**)&q,      g_q);
    cudaGetSymbolAddress((void**)&k,      g_k);
    cudaGetSymbolAddress((void**)&v,      g_v);
    cudaGetSymbolAddress((void**)&att,    g_att);
    cudaGetSymbolAddress((void**)&t0,     g_t0);
    cudaGetSymbolAddress((void**)&t1,     g_t1);
    cudaGetSymbolAddress((void**)&t2,     g_t2);
    cudaGetSymbolAddress((void**)&w,      g_w);
    cudaGetSymbolAddress((void**)&logits, g_logits);
    cudaGetSymbolAddress((void**)&A1, g_A1);
    cudaGetSymbolAddress((void**)&B1, g_B1);
    cudaGetSymbolAddress((void**)&A2, g_A2);
    cudaGetSymbolAddress((void**)&B2, g_B2);

    static bool attr_set = false;
    if (!attr_set) {
        cudaFuncSetAttribute(gemm_f16_kernel, cudaFuncAttributeMaxDynamicSharedMemorySize,
                             FNSTAGE * FSTAGE);
        attr_set = true;
    }

    // weight prep (independent of activations)
    transpose_half_kernel<<<dim3(CLS_H / 32, Ee / 32), 256>>>(cls_w1, B1, Ee, CLS_H);
    transpose_half_kernel<<<dim3(VOC_PAD / 32, CLS_H / 32), 256>>>(cls_w2, B2, CLS_H, VOC);

    // embeddings + positional encoding
    embed_kernel<<<ROWS, 256>>>(src_ids, src_emb, x);
    embed_kernel<<<ROWS, 256>>>(tgt_ids, tgt_emb, y);

    #define RUN_MHA(Xk, Xv, Xq, wk_, wv_, wq_, dw_, db_, OUT, CAUSAL)              \
        do {                                                                       \
            repack_kernel<<<Ee, 256>>>((wq_), w);                                  \
            launch_gemm((Xq), w, nullptr, q, ROWS, Ee, Ee, 0);                     \
            repack_kernel<<<Ee, 256>>>((wk_), w);                                  \
            launch_gemm((Xk), w, nullptr, k, ROWS, Ee, Ee, 0);                     \
            repack_kernel<<<Ee, 256>>>((wv_), w);                                  \
            launch_gemm((Xv), w, nullptr, v, ROWS, Ee, Ee, 0);                     \
            qk_kernel<<<dim3(8, 8, Bb * NH), 256>>>(q, k, logits, (CAUSAL));       \
            softmax_kernel<<<Bb * NH * Ss, 256>>>(logits);                         \
            pv_kernel<<<dim3(8, Bb * NH), 256>>>(logits, v, att);                  \
            launch_gemm(att, (dw_), (db_), (OUT), ROWS, Ee, Ee, 0);                \
        } while (0)

    // ---- encoder ----
    RUN_MHA(x, x, x, enc_wk, enc_wv, enc_wq, enc_dw, enc_db, t0, 1);
    ln_kernel<<<ROWS, 256>>>(x, t0, enc_ln_g, enc_ln_b, t1, 0);
    launch_gemm(t1, enc_ffw, enc_ffb, t2, ROWS, Ee, Ee, 0);
    ln_kernel<<<ROWS, 256>>>(t1, t2, enc_ln_g, enc_ln_b, x, 0);

    // ---- decoder ----
    RUN_MHA(y, y, y, dec_swk, dec_swv, dec_swq, dec_sdw, dec_sdb, t0, 1);
    ln_kernel<<<ROWS, 256>>>(t0, y, dec_ln_g, dec_ln_b, t1, 0);
    RUN_MHA(x, x, t1, dec_cwk, dec_cwv, dec_cwq, dec_cdw, dec_cdb, t0, 0);
    ln_kernel<<<ROWS, 256>>>(t0, t1, dec_ln_g, dec_ln_b, t2, 0);
    launch_gemm(t2, dec_ffw, dec_ffb, t0, ROWS, Ee, Ee, 0);
    ln_kernel<<<ROWS, 256>>>(t0, t2, dec_ln_g, dec_ln_b, t1, 1);  // dec_out

    // ---- classifier GEMM1 (single fp16): hid = relu(dec_out@w1 + b1) -> fp16
    to_half_kernel<<<(ROWS * Ee / 4 + 255) / 256, 256>>>(t1, A1, ROWS * Ee);
    gemm_f16_kernel<<<(ROWS / 128) * (CLS_H / 128), 256, FNSTAGE * FSTAGE>>>(
        A1, B1, cls_b1, nullptr, A2,
        Ee, Ee, CLS_H / 128, CLS_H, CLS_H, 0);

    // ---- classifier GEMM2 (single fp16): out = hid@w2 + b2
    gemm_f16_kernel<<<(ROWS / 128) * (VOC_PAD / 128), 256, FNSTAGE * FSTAGE>>>(
        A2, B2, cls_b2, (float*)d_out, nullptr,
        CLS_H, CLS_H, VOC_PAD / 128, VOC, VOC, 1);
}

// round 16
// speedup vs baseline: 5.5773x; 1.1567x over previous
#include <cuda_runtime.h>
#include <cuda_fp16.h>
#include <math.h>
#include <stdint.h>

// Problem dims
#define Bb 8
#define Ss 512
#define Ee 512
#define NH 8
#define HDm 64
#define ROWS (Bb*Ss)        // 4096 token rows
#define CLS_H 16000
#define VOC 8000
#define VOC_PAD 8064
#define SQRT_E 22.627416997969522f
#define QK_SCALE 0.04419417382415922f   // 1/sqrt(512)
#define LN_EPS 1e-3f

// ---------------- scratch (device globals; no allocations allowed) -------------
__device__ float g_x[ROWS*Ee];
__device__ float g_y[ROWS*Ee];
__device__ float g_q[ROWS*Ee];
__device__ float g_k[ROWS*Ee];
__device__ float g_v[ROWS*Ee];
__device__ float g_att[ROWS*Ee];
__device__ float g_t0[ROWS*Ee];
__device__ float g_t1[ROWS*Ee];
__device__ float g_t2[ROWS*Ee];
__device__ float g_logits[Bb*NH*Ss*Ss];

// fp16 activation/weight buffers for HMMA glue
__device__ __half g_hx[ROWS*Ee];     // K/V-source activations fp16
__device__ __half g_hq[ROWS*Ee];     // Q-source activations fp16
__device__ __half g_hatt[ROWS*Ee];   // attention output fp16
__device__ __half g_hw[Ee*Ee];       // current weight fp16 [N,K]

// classifier fp16 buffers
__device__ __half g_A1[ROWS*Ee];               // dec_out fp16 [4096,512]
__device__ __half g_B1[(size_t)CLS_H*Ee];      // w1^T fp16 [16000,512]
__device__ __half g_A2[(size_t)ROWS*CLS_H];    // hidden fp16 [4096,16000]
__device__ __half g_B2[(size_t)VOC_PAD*CLS_H]; // w2^T fp16 padded [8064,16000]

// ================= helpers =================
__device__ __forceinline__ uint32_t smem_u32(const void* p) {
    uint32_t a;
    asm("{ .reg .u64 t; cvta.to.shared.u64 t, %1; cvt.u32.u64 %0, t; }" : "=r"(a) : "l"(p));
    return a;
}
__device__ __forceinline__ void cp16(uint32_t dst, const void* src) {
    asm volatile("cp.async.cg.shared.global [%0], [%1], 16;" :: "r"(dst), "l"(src));
}
__device__ __forceinline__ void cp_commit() { asm volatile("cp.async.commit_group;"); }
__device__ __forceinline__ void cp_wait1()  { asm volatile("cp.async.wait_group 1;"); }

__device__ __forceinline__ void ldsm4(uint32_t* r, uint32_t addr) {
    asm volatile("ldmatrix.sync.aligned.m8n8.x4.shared.b16 {%0,%1,%2,%3}, [%4];"
        : "=r"(r[0]), "=r"(r[1]), "=r"(r[2]), "=r"(r[3]) : "r"(addr));
}
__device__ __forceinline__ void mma_f16(float* c, const uint32_t* a, const uint32_t* b) {
    asm volatile("mma.sync.aligned.m16n8k16.row.col.f32.f16.f16.f32 "
        "{%0,%1,%2,%3}, {%4,%5,%6,%7}, {%8,%9}, {%0,%1,%2,%3};"
        : "+f"(c[0]), "+f"(c[1]), "+f"(c[2]), "+f"(c[3])
        : "r"(a[0]), "r"(a[1]), "r"(a[2]), "r"(a[3]), "r"(b[0]), "r"(b[1]));
}

// ================= unified fp16 HMMA GEMM =================
// C[M,N] = A[M,K] @ B[N,K]^T (+bias if non-null)
// mode 0: relu -> fp16 store (outh)
// mode 1: fp32 store guarded col<Nreal
#define FMAT 10240                 // 128*40*2
#define FSTAGE (2*FMAT)            // 20480
#define FNSTAGE 3

__device__ __forceinline__ void load_stage_f16(
    uint32_t sb, const __half* A, const __half* B,
    size_t m0, size_t n0, int k0, int ld, int t)
{
    const __half* srcs[2] = { A, B };
    #pragma unroll
    for (int p = 0; p < 4; p++) {
        int idx = t + p * 256;        // 0..1023
        int mat = idx >> 9;           // 0..1
        int r   = (idx & 511) >> 2;   // 0..127
        int ch  = idx & 3;
        size_t grow = (mat == 0 ? m0 : n0) + r;
        cp16(sb + mat * FMAT + r * 80 + ch * 16,
             srcs[mat] + grow * (size_t)ld + k0 + ch * 8);
    }
}

__global__ void __launch_bounds__(256, 2) gemm_f16_kernel(
    const __half* __restrict__ A, const __half* __restrict__ B,
    const float* __restrict__ bias, float* __restrict__ outf,
    __half* __restrict__ outh,
    int K, int ld, int tiles_n, int Nreal, int ldo, int mode)
{
    extern __shared__ char smem[];
    uint32_t sbase = smem_u32(smem);
    const int t = threadIdx.x;
    const int wid = t >> 5, lane = t & 31;
    const int warp_m = wid & 1, warp_n = wid >> 1;   // 2x4 warps, warp tile 64x32

    const int G = 8;
    int idx = blockIdx.x;
    int band = idx / (G * tiles_n);
    int r = idx % (G * tiles_n);
    size_t m0 = (size_t)(band * G + (r % G)) * 128;
    size_t n0 = (size_t)(r / G) * 128;

    float acc[4][4][4];
    #pragma unroll
    for (int i = 0; i < 4; i++)
        #pragma unroll
        for (int j = 0; j < 4; j++)
            #pragma unroll
            for (int e = 0; e < 4; e++) acc[i][j][e] = 0.0f;

    const int C = K >> 5;
    load_stage_f16(sbase + 0 * FSTAGE, A, B, m0, n0, 0,  ld, t); cp_commit();
    load_stage_f16(sbase + 1 * FSTAGE, A, B, m0, n0, 32, ld, t); cp_commit();

    const int lrow = lane & 15;
    const int lcolb = (lane >> 4) * 16;

    for (int c = 0; c < C; c++) {
        cp_wait1();
        __syncthreads();
        if (c + 2 < C)
            load_stage_f16(sbase + ((c + 2) % FNSTAGE) * FSTAGE,
                           A, B, m0, n0, (c + 2) * 32, ld, t);
        cp_commit();

        uint32_t sb = sbase + (c % FNSTAGE) * FSTAGE;
        uint32_t aBase = sb +        (warp_m * 64 + lrow) * 80;
        uint32_t bBase = sb + FMAT + (warp_n * 32 + lrow) * 80;

        #pragma unroll
        for (int ks = 0; ks < 2; ks++) {
            int kb = ks * 32 + lcolb;
            uint32_t af[4][4], bf[4][2];
            #pragma unroll
            for (int fm = 0; fm < 4; fm++)
                ldsm4(af[fm], aBase + fm * 16 * 80 + kb);
            #pragma unroll
            for (int fp = 0; fp < 2; fp++) {
                uint32_t rr[4];
                ldsm4(rr, bBase + fp * 16 * 80 + kb);
                bf[fp*2][0] = rr[0]; bf[fp*2][1] = rr[2];
                bf[fp*2+1][0] = rr[1]; bf[fp*2+1][1] = rr[3];
            }
            #pragma unroll
            for (int fm = 0; fm < 4; fm++)
                #pragma unroll
                for (int fn = 0; fn < 4; fn++)
                    mma_f16(acc[fm][fn], af[fm], bf[fn]);
        }
        __syncthreads();
    }

    const int g = lane >> 2;
    const int cq = (lane & 3) * 2;
    #pragma unroll
    for (int fm = 0; fm < 4; fm++) {
        #pragma unroll
        for (int fn = 0; fn < 4; fn++) {
            int colbase = (int)n0 + warp_n * 32 + fn * 8 + cq;
            float b0 = 0.0f, b1 = 0.0f;
            if (bias && colbase < Nreal) { b0 = bias[colbase]; b1 = bias[colbase + 1]; }
            if (mode == 0) {
                #pragma unroll
                for (int hrow = 0; hrow < 2; hrow++) {
                    size_t row = m0 + warp_m * 64 + fm * 16 + g + hrow * 8;
                    float v0 = fmaxf(acc[fm][fn][hrow * 2 + 0] + b0, 0.0f);
                    float v1 = fmaxf(acc[fm][fn][hrow * 2 + 1] + b1, 0.0f);
                    __half2 hv;
                    hv.x = __float2half(v0);
                    hv.y = __float2half(v1);
                    *reinterpret_cast<__half2*>(&outh[row * (size_t)ldo + colbase]) = hv;
                }
            } else {
                if (colbase < Nreal) {
                    #pragma unroll
                    for (int hrow = 0; hrow < 2; hrow++) {
                        size_t row = m0 + warp_m * 64 + fm * 16 + g + hrow * 8;
                        float2 fv;
                        fv.x = acc[fm][fn][hrow * 2 + 0] + b0;
                        fv.y = acc[fm][fn][hrow * 2 + 1] + b1;
                        *reinterpret_cast<float2*>(&outf[row * (size_t)ldo + colbase]) = fv;
                    }
                }
            }
        }
    }
}

// ---------------- fp32 -> fp16 elementwise ----------------
__global__ __launch_bounds__(256) void to_half_kernel(
    const float* __restrict__ in, __half* __restrict__ out, int count)
{
    int i = (blockIdx.x * 256 + threadIdx.x) * 4;
    if (i < count) {
        float4 v = *reinterpret_cast<const float4*>(&in[i]);
        __half2 h0, h1;
        h0.x = __float2half(v.x); h0.y = __float2half(v.y);
        h1.x = __float2half(v.z); h1.y = __float2half(v.w);
        *reinterpret_cast<__half2*>(&out[i])     = h0;
        *reinterpret_cast<__half2*>(&out[i + 2]) = h1;
    }
}

// ---------------- transpose to fp16: fp32 [K,N] -> fp16 [Npad,K] ----------------
__global__ __launch_bounds__(256) void transpose_half_kernel(
    const float* __restrict__ in, __half* __restrict__ out, int K, int N)
{
    __shared__ float tile[32][33];
    int n0 = blockIdx.x * 32, k0 = blockIdx.y * 32;
    int tx = threadIdx.x & 31, ty = threadIdx.x >> 5;
    #pragma unroll
    for (int j = 0; j < 4; j++) {
        int kk = k0 + ty + j * 8;
        int nn = n0 + tx;
        tile[ty + j * 8][tx] = (nn < N) ? in[(size_t)kk * N + nn] : 0.0f;
    }
    __syncthreads();
    #pragma unroll
    for (int j = 0; j < 4; j++) {
        int nn = n0 + ty + j * 8;
        int kk = k0 + tx;
        out[(size_t)nn * K + kk] = __float2half(tile[tx][ty + j * 8]);
    }
}

// ---------------- head weights [H,E,HD] -> fp16 B[N=H*HD][K=E] ----------------
__global__ __launch_bounds__(256) void repackT_half_kernel(
    const float* __restrict__ in, __half* __restrict__ out)
{
    __shared__ float tile[32][33];
    int j0 = blockIdx.x * 32, e0 = blockIdx.y * 32;
    int tx = threadIdx.x & 31, ty = threadIdx.x >> 5;
    // load: rows = e (ty), cols = j (tx); in[(j>>6)*E*HD + e*HD + (j&63)]
    #pragma unroll
    for (int jj = 0; jj < 4; jj++) {
        int e = e0 + ty + jj * 8;
        int j = j0 + tx;
        tile[ty + jj * 8][tx] = in[(j >> 6) * (Ee * HDm) + e * HDm + (j & 63)];
    }
    __syncthreads();
    // write: out[j][e], coalesced over e=tx
    #pragma unroll
    for (int jj = 0; jj < 4; jj++) {
        int j = j0 + ty + jj * 8;
        int e = e0 + tx;
        out[(size_t)j * Ee + e] = __float2half(tile[tx][ty + jj * 8]);
    }
}

// ---------------- embedding + positional encoding ----------------
__global__ __launch_bounds__(256) void embed_kernel(
    const int* __restrict__ ids, const float* __restrict__ emb, float* __restrict__ out)
{
    int bs = blockIdx.x;
    int s  = bs & (Ss - 1);
    int id = ids[bs];
    const float* erow = emb + (size_t)id * Ee;
    float* orow = out + (size_t)bs * Ee;
    for (int e = threadIdx.x; e < Ee; e += blockDim.x) {
        int i = e & 255;
        float rate = expf(-(float)i * (9.210340371976184f / 256.0f));
        float ang = (float)s * rate;
        float p = (e < 256) ? sinf(ang) : cosf(ang);
        orow[e] = erow[e] * SQRT_E + p;
    }
}

// ---------------- QK^T + scale + causal ----------------
__global__ __launch_bounds__(256) void qk_kernel(
    const float* __restrict__ Q, const float* __restrict__ Km,
    float* __restrict__ L, int causal)
{
    __shared__ float Qs[64][68];
    __shared__ float Ks[64][68];
    int bh = blockIdx.z, b = bh >> 3, h = bh & 7;
    int q0 = blockIdx.y * 64, k0 = blockIdx.x * 64;
    int t = threadIdx.x;
    #pragma unroll
    for (int p = 0; p < 4; p++) {
        int idx = t + p * 256;
        int r = idx >> 4, f4 = (idx & 15) * 4;
        *reinterpret_cast<float4*>(&Qs[r][f4]) =
            *reinterpret_cast<const float4*>(&Q[(size_t)(b * Ss + q0 + r) * Ee + h * HDm + f4]);
        *reinterpret_cast<float4*>(&Ks[r][f4]) =
            *reinterpret_cast<const float4*>(&Km[(size_t)(b * Ss + k0 + r) * Ee + h * HDm + f4]);
    }
    __syncthreads();
    int tx = t & 15, ty = t >> 4;
    float acc[4][4] = {};
    #pragma unroll 4
    for (int d = 0; d < 64; d++) {
        float ra[4], rb[4];
        #pragma unroll
        for (int i = 0; i < 4; i++) ra[i] = Qs[ty * 4 + i][d];
        #pragma unroll
        for (int j = 0; j < 4; j++) rb[j] = Ks[tx * 4 + j][d];
        #pragma unroll
        for (int i = 0; i < 4; i++)
            #pragma unroll
            for (int j = 0; j < 4; j++)
                acc[i][j] += ra[i] * rb[j];
    }
    #pragma unroll
    for (int i = 0; i < 4; i++) {
        int qi = q0 + ty * 4 + i;
        #pragma unroll
        for (int j = 0; j < 4; j++) {
            int ki = k0 + tx * 4 + j;
            float v = acc[i][j] * QK_SCALE;
            if (causal && ki > qi) v = -INFINITY;
            L[((size_t)bh * Ss + qi) * Ss + ki] = v;
        }
    }
}

// ---------------- row softmax ----------------
__global__ __launch_bounds__(256) void softmax_kernel(float* __restrict__ L)
{
    __shared__ float red[256];
    float* row = L + (size_t)blockIdx.x * Ss;
    int t = threadIdx.x;
    float a = row[t], b = row[t + 256];
    red[t] = fmaxf(a, b);
    __syncthreads();
    for (int s = 128; s > 0; s >>= 1) { if (t < s) red[t] = fmaxf(red[t], red[t + s]); __syncthreads(); }
    float m = red[0];
    __syncthreads();
    float e0 = expf(a - m), e1 = expf(b - m);
    red[t] = e0 + e1;
    __syncthreads();
    for (int s = 128; s > 0; s >>= 1) { if (t < s) red[t] += red[t + s]; __syncthreads(); }
    float inv = 1.0f / red[0];
    row[t] = e0 * inv;
    row[t + 256] = e1 * inv;
}

// ---------------- P @ V ----------------
__global__ __launch_bounds__(256) void pv_kernel(
    const float* __restrict__ P, const float* __restrict__ V, float* __restrict__ O)
{
    __shared__ float Ps[64][68];
    __shared__ float Vs[64][68];
    int bh = blockIdx.y, b = bh >> 3, h = bh & 7;
    int q0 = blockIdx.x * 64;
    int t = threadIdx.x, tx = t & 15, ty = t >> 4;
    float acc[4][4] = {};
    for (int k0 = 0; k0 < Ss; k0 += 64) {
        #pragma unroll
        for (int p = 0; p < 4; p++) {
            int idx = t + p * 256;
            int r = idx >> 4, f4 = (idx & 15) * 4;
            *reinterpret_cast<float4*>(&Ps[r][f4]) =
                *reinterpret_cast<const float4*>(&P[((size_t)bh * Ss + q0 + r) * Ss + k0 + f4]);
            *reinterpret_cast<float4*>(&Vs[r][f4]) =
                *reinterpret_cast<const float4*>(&V[(size_t)(b * Ss + k0 + r) * Ee + h * HDm + f4]);
        }
        __syncthreads();
        #pragma unroll 4
        for (int kk = 0; kk < 64; kk++) {
            float ra[4], rb[4];
            #pragma unroll
            for (int i = 0; i < 4; i++) ra[i] = Ps[ty * 4 + i][kk];
            #pragma unroll
            for (int j = 0; j < 4; j++) rb[j] = Vs[kk][tx * 4 + j];
            #pragma unroll
            for (int i = 0; i < 4; i++)
                #pragma unroll
                for (int j = 0; j < 4; j++)
                    acc[i][j] += ra[i] * rb[j];
        }
        __syncthreads();
    }
    #pragma unroll
    for (int i = 0; i < 4; i++)
        #pragma unroll
        for (int j = 0; j < 4; j++)
            O[(size_t)(b * Ss + q0 + ty * 4 + i) * Ee + h * HDm + tx * 4 + j] = acc[i][j];
}

// ---------------- LN(A + R)*g + b (opt relu) ----------------
__global__ __launch_bounds__(256) void ln_kernel(
    const float* __restrict__ A, const float* __restrict__ R,
    const float* __restrict__ g, const float* __restrict__ be,
    float* __restrict__ out, int relu)
{
    __shared__ float red[256];
    size_t row = blockIdx.x;
    int t = threadIdx.x;
    float a0 = A[row * Ee + t] + R[row * Ee + t];
    float a1 = A[row * Ee + t + 256] + R[row * Ee + t + 256];
    red[t] = a0 + a1;
    __syncthreads();
    for (int s = 128; s > 0; s >>= 1) { if (t < s) red[t] += red[t + s]; __syncthreads(); }
    float mean = red[0] * (1.0f / Ee);
    __syncthreads();
    float d0 = a0 - mean, d1 = a1 - mean;
    red[t] = d0 * d0 + d1 * d1;
    __syncthreads();
    for (int s = 128; s > 0; s >>= 1) { if (t < s) red[t] += red[t + s]; __syncthreads(); }
    float var = red[0] * (1.0f / Ee);
    float inv = rsqrtf(var + LN_EPS);
    float v0 = d0 * inv * g[t] + be[t];
    float v1 = d1 * inv * g[t + 256] + be[t + 256];
    if (relu) { v0 = fmaxf(v0, 0.0f); v1 = fmaxf(v1, 0.0f); }
    out[row * Ee + t] = v0;
    out[row * Ee + t + 256] = v1;
}

// ---------------- host orchestration ----------------
extern "C" void kernel_launch(void* const* d_in, const int* in_sizes, int n_in,
                              void* d_out, int out_size)
{
    const int*   src_ids  = (const int*)  d_in[0];
    const int*   tgt_ids  = (const int*)  d_in[1];
    const float* src_emb  = (const float*)d_in[2];
    const float* tgt_emb  = (const float*)d_in[3];
    const float* enc_wk   = (const float*)d_in[4];
    const float* enc_wv   = (const float*)d_in[5];
    const float* enc_wq   = (const float*)d_in[6];
    const float* enc_dw   = (const float*)d_in[7];
    const float* enc_db   = (const float*)d_in[8];
    const float* enc_ffw  = (const float*)d_in[9];
    const float* enc_ffb  = (const float*)d_in[10];
    const float* enc_ln_g = (const float*)d_in[11];
    const float* enc_ln_b = (const float*)d_in[12];
    const float* dec_swk  = (const float*)d_in[13];
    const float* dec_swv  = (const float*)d_in[14];
    const float* dec_swq  = (const float*)d_in[15];
    const float* dec_sdw  = (const float*)d_in[16];
    const float* dec_sdb  = (const float*)d_in[17];
    const float* dec_cwk  = (const float*)d_in[18];
    const float* dec_cwv  = (const float*)d_in[19];
    const float* dec_cwq  = (const float*)d_in[20];
    const float* dec_cdw  = (const float*)d_in[21];
    const float* dec_cdb  = (const float*)d_in[22];
    const float* dec_ffw  = (const float*)d_in[23];
    const float* dec_ffb  = (const float*)d_in[24];
    const float* dec_ln_g = (const float*)d_in[25];
    const float* dec_ln_b = (const float*)d_in[26];
    const float* cls_w1   = (const float*)d_in[27];
    const float* cls_b1   = (const float*)d_in[28];
    const float* cls_w2   = (const float*)d_in[29];
    const float* cls_b2   = (const float*)d_in[30];

    float *x, *y, *q, *k, *v, *att, *t0, *t1, *t2, *logits;
    __half *hx, *hq, *hatt, *hw, *A1, *B1, *A2, *B2;
    cudaGetSymbolAddress((void**)&x,      g_x);
    cudaGetSymbolAddress((void**)&y,      g_y);
    cudaGetSymbolAddress((void**)&q,      g_q);
    cudaGetSymbolAddress((void**)&k,      g_k);
    cudaGetSymbolAddress((void**)&v,      g_v);
    cudaGetSymbolAddress((void**)&att,    g_att);
    cudaGetSymbolAddress((void**)&t0,     g_t0);
    cudaGetSymbolAddress((void**)&t1,     g_t1);
    cudaGetSymbolAddress((void**)&t2,     g_t2);
    cudaGetSymbolAddress((void**)&logits, g_logits);
    cudaGetSymbolAddress((void**)&hx,   g_hx);
    cudaGetSymbolAddress((void**)&hq,   g_hq);
    cudaGetSymbolAddress((void**)&hatt, g_hatt);
    cudaGetSymbolAddress((void**)&hw,   g_hw);
    cudaGetSymbolAddress((void**)&A1, g_A1);
    cudaGetSymbolAddress((void**)&B1, g_B1);
    cudaGetSymbolAddress((void**)&A2, g_A2);
    cudaGetSymbolAddress((void**)&B2, g_B2);

    static bool attr_set = false;
    if (!attr_set) {
        cudaFuncSetAttribute(gemm_f16_kernel, cudaFuncAttributeMaxDynamicSharedMemorySize,
                             FNSTAGE * FSTAGE);
        attr_set = true;
    }
    const int TCS = FNSTAGE * FSTAGE;

    // fp16 glue GEMM: C[4096,512] = A@B^T (+bias), fp32 out
    #define GEMM_E(Ain, Bin, biasp, Cout)                                          \
        gemm_f16_kernel<<<(ROWS / 128) * (Ee / 128), 256, TCS>>>(                  \
            (Ain), (Bin), (biasp), (Cout), nullptr, Ee, Ee, Ee / 128, Ee, Ee, 1)

    // weight prep (independent of activations)
    transpose_half_kernel<<<dim3(CLS_H / 32, Ee / 32), 256>>>(cls_w1, B1, Ee, CLS_H);
    transpose_half_kernel<<<dim3(VOC_PAD / 32, CLS_H / 32), 256>>>(cls_w2, B2, CLS_H, VOC);

    // embeddings + positional encoding
    embed_kernel<<<ROWS, 256>>>(src_ids, src_emb, x);
    embed_kernel<<<ROWS, 256>>>(tgt_ids, tgt_emb, y);

    // Xkv = K/V source (fp32), Xq = Q source (fp32)
    #define RUN_MHA(Xkv, Xq, wk_, wv_, wq_, dw_, db_, OUT, CAUSAL)                 \
        do {                                                                       \
            to_half_kernel<<<(ROWS * Ee / 4 + 255) / 256, 256>>>((Xkv), hx, ROWS * Ee); \
            to_half_kernel<<<(ROWS * Ee / 4 + 255) / 256, 256>>>((Xq),  hq, ROWS * Ee); \
            repackT_half_kernel<<<dim3(Ee / 32, Ee / 32), 256>>>((wq_), hw);       \
            GEMM_E(hq, hw, nullptr, q);                                            \
            repackT_half_kernel<<<dim3(Ee / 32, Ee / 32), 256>>>((wk_), hw);       \
            GEMM_E(hx, hw, nullptr, k);                                            \
            repackT_half_kernel<<<dim3(Ee / 32, Ee / 32), 256>>>((wv_), hw);       \
            GEMM_E(hx, hw, nullptr, v);                                            \
            qk_kernel<<<dim3(8, 8, Bb * NH), 256>>>(q, k, logits, (CAUSAL));       \
            softmax_kernel<<<Bb * NH * Ss, 256>>>(logits);                         \
            pv_kernel<<<dim3(8, Bb * NH), 256>>>(logits, v, att);                  \
            to_half_kernel<<<(ROWS * Ee / 4 + 255) / 256, 256>>>(att, hatt, ROWS * Ee); \
            transpose_half_kernel<<<dim3(Ee / 32, Ee / 32), 256>>>((dw_), hw, Ee, Ee); \
            GEMM_E(hatt, hw, (db_), (OUT));                                        \
        } while (0)

    // ---- encoder ----
    RUN_MHA(x, x, enc_wk, enc_wv, enc_wq, enc_dw, enc_db, t0, 1);
    ln_kernel<<<ROWS, 256>>>(x, t0, enc_ln_g, enc_ln_b, t1, 0);
    to_half_kernel<<<(ROWS * Ee / 4 + 255) / 256, 256>>>(t1, hx, ROWS * Ee);
    transpose_half_kernel<<<dim3(Ee / 32, Ee / 32), 256>>>(enc_ffw, hw, Ee, Ee);
    GEMM_E(hx, hw, enc_ffb, t2);
    ln_kernel<<<ROWS, 256>>>(t1, t2, enc_ln_g, enc_ln_b, x, 0);

    // ---- decoder ----
    RUN_MHA(y, y, dec_swk, dec_swv, dec_swq, dec_sdw, dec_sdb, t0, 1);
    ln_kernel<<<ROWS, 256>>>(t0, y, dec_ln_g, dec_ln_b, t1, 0);
    RUN_MHA(x, t1, dec_cwk, dec_cwv, dec_cwq, dec_cdw, dec_cdb, t0, 0);
    ln_kernel<<<ROWS, 256>>>(t0, t1, dec_ln_g, dec_ln_b, t2, 0);
    to_half_kernel<<<(ROWS * Ee / 4 + 255) / 256, 256>>>(t2, hx, ROWS * Ee);
    transpose_half_kernel<<<dim3(Ee / 32, Ee / 32), 256>>>(dec_ffw, hw, Ee, Ee);
    GEMM_E(hx, hw, dec_ffb, t0);
    ln_kernel<<<ROWS, 256>>>(t0, t2, dec_ln_g, dec_ln_b, t1, 1);  // dec_out

    // ---- classifier GEMM1 (single fp16): hid = relu(dec_out@w1 + b1) -> fp16
    to_half_kernel<<<(ROWS * Ee / 4 + 255) / 256, 256>>>(t1, A1, ROWS * Ee);
    gemm_f16_kernel<<<(ROWS / 128) * (CLS_H / 128), 256, TCS>>>(
        A1, B1, cls_b1, nullptr, A2,
        Ee, Ee, CLS_H / 128, CLS_H, CLS_H, 0);

    // ---- classifier GEMM2 (single fp16): out = hid@w2 + b2
    gemm_f16_kernel<<<(ROWS / 128) * (VOC_PAD / 128), 256, TCS>>>(
        A2, B2, cls_b2, (float*)d_out, nullptr,
        CLS_H, CLS_H, VOC_PAD / 128, VOC, VOC, 1);

    #undef RUN_MHA
    #undef GEMM_E
}